// round 12
// baseline (speedup 1.0000x reference)
#include <cuda_runtime.h>
#include <math.h>
#include <stdint.h>

// ---------------- problem constants ----------------
#define NBT 512
#define NN 64
#define DD 128
#define HH 4
#define DHH 32
#define LL 3
#define D4 512
#define NROWS (NBT*NN)     // 32768
#define MAXE 4096

// packed weight offsets (u32 units; layout [K/2][N] k2-major)
#define WOFF_WP   0
#define WSEG      90112                     // per-layer packed size
#define WOFF_LIN(l)  (8192 + (l)*WSEG)
#define WOFF_VAL(l)  (8192 + (l)*WSEG + 8192)
#define WOFF_OUT(l)  (8192 + (l)*WSEG + 16384)
#define WOFF_M1(l)   (8192 + (l)*WSEG + 24576)
#define WOFF_M2(l)   (8192 + (l)*WSEG + 57344)
#define WTOT      (8192 + LL*WSEG)          // 278528

// ---------------- scratch (device globals; no allocation) ----------------
__device__ float g_Z    [NROWS*DD];
__device__ float g_Hmix [NROWS*DD];
__device__ float g_Xq   [NROWS*DD];
__device__ float g_Xv   [NROWS*DD];
__device__ float g_U    [NROWS*DD];
__device__ float g_A    [NN*NN];
__device__ float g_logA0[MAXE];
__device__ int   g_rowptr[NN+1];
__device__ float g_mu1[NROWS], g_rs1[NROWS], g_mu2[NROWS], g_rs2[NROWS];
// packed bf16 hi/lo activations
__device__ uint32_t g_XH [NROWS*64],  g_XL [NROWS*64];
__device__ uint32_t g_ZH [NROWS*64],  g_ZL [NROWS*64];
__device__ uint32_t g_YH [NROWS*64],  g_YL [NROWS*64];
__device__ uint32_t g_UgH[NROWS*64],  g_UgL[NROWS*64];
__device__ uint32_t g_M1H[NROWS*256], g_M1L[NROWS*256];
// packed weights
__device__ uint32_t g_WH[WTOT], g_WL[WTOT];
// LN epilogue vectors
#define VECL (DD + DD + D4)
__device__ float g_CS[LL*VECL];
__device__ float g_US[LL*VECL];

// ---------------- helpers ----------------
__device__ __forceinline__ uint32_t smem_u32(const void* p) {
    uint32_t a;
    asm("{ .reg .u64 t; cvta.to.shared.u64 t, %1; cvt.u32.u64 %0, t; }" : "=r"(a) : "l"(p));
    return a;
}
__device__ __forceinline__ void cp_async16(void* smem, const void* gmem) {
    unsigned sa = smem_u32(smem);
    asm volatile("cp.async.cg.shared.global [%0], [%1], 16;\n" :: "r"(sa), "l"(gmem));
}
__device__ __forceinline__ uint32_t pack_bf16x2(float x0, float x1) {
    uint32_t r;
    asm("cvt.rn.bf16x2.f32 %0, %1, %2;" : "=r"(r) : "f"(x1), "f"(x0));
    return r;
}
__device__ __forceinline__ void split_pair(float x0, float x1, uint32_t& h2, uint32_t& l2) {
    h2 = pack_bf16x2(x0, x1);
    float h0 = __uint_as_float(h2 << 16);
    float h1 = __uint_as_float(h2 & 0xffff0000u);
    l2 = pack_bf16x2(x0 - h0, x1 - h1);
}
__device__ __forceinline__ void mma_bf16(float* c, const uint32_t* a, const uint32_t* b) {
    asm volatile("mma.sync.aligned.m16n8k16.row.col.f32.bf16.bf16.f32 "
        "{%0,%1,%2,%3}, {%4,%5,%6,%7}, {%8,%9}, {%0,%1,%2,%3};"
        : "+f"(c[0]), "+f"(c[1]), "+f"(c[2]), "+f"(c[3])
        : "r"(a[0]), "r"(a[1]), "r"(a[2]), "r"(a[3]), "r"(b[0]), "r"(b[1]));
}

// ---------------- bf16x3 GEMM: pre-packed A and B, 3-stage pipeline ---------
// C(fp32, opt) / Ch,Cl(packed, opt) = act( [LN-epi]( A@B ) + bias ) + add1 + add2
#define ASTP 12        // smem A row stride (u32, 8 used + 4 pad): conflict-free
#define BSTP 136       // smem B k2-row stride (u32): conflict-free
#define A_BUF (128*ASTP)       // 1536 u32
#define B_BUF (8*BSTP)         // 1088 u32
#define STG_U32 (2*A_BUF + 2*B_BUF)   // 5248
#define GEMM_SMEM (3*STG_U32*4)       // 62976 B

extern __shared__ uint32_t dynsm[];
__global__ __launch_bounds__(256) void hgemm_kernel(
    const uint32_t* __restrict__ Ah, const uint32_t* __restrict__ Al, int wOff,
    float* __restrict__ C, uint32_t* __restrict__ Ch, uint32_t* __restrict__ Cl,
    int M, int K, int N,
    const float* __restrict__ bias, const float* __restrict__ add1,
    const float* __restrict__ add2, int act,
    const float* __restrict__ emu, const float* __restrict__ ers,
    const float* __restrict__ ecs, const float* __restrict__ eu)
{
    const int tid  = threadIdx.x;
    const int lane = tid & 31;
    const int wid  = tid >> 5;
    const int wm = (wid & 1) * 64;
    const int wn = (wid >> 1) * 32;
    const int bm = blockIdx.y * 128;
    const int bn = blockIdx.x * 128;
    const int K2 = K >> 1;
    const int nt = K / 16;

    // load-thread roles
    const int arow = tid >> 1;            // 0..127
    const int ahalf = (tid & 1) * 4;      // u32 offset 0 or 4
    const int bk2  = tid >> 5;            // 0..7
    const int bc4  = (tid & 31) * 4;

    const uint32_t* Whg = g_WH + wOff + bn;
    const uint32_t* Wlg = g_WL + wOff + bn;
    const uint32_t* Ahg = Ah + (size_t)bm * K2;
    const uint32_t* Alg = Al + (size_t)bm * K2;

    float c[4][4][4];
    #pragma unroll
    for (int mi = 0; mi < 4; mi++)
        #pragma unroll
        for (int ni = 0; ni < 4; ni++)
            #pragma unroll
            for (int q = 0; q < 4; q++) c[mi][ni][q] = 0.f;

#define ISSUE(t)                                                                    \
    {                                                                               \
        uint32_t* S = dynsm + ((t) % 3) * STG_U32;                                  \
        cp_async16(S + arow * ASTP + ahalf,                                         \
                   Ahg + (size_t)arow * K2 + (t) * 8 + ahalf);                      \
        cp_async16(S + A_BUF + arow * ASTP + ahalf,                                 \
                   Alg + (size_t)arow * K2 + (t) * 8 + ahalf);                      \
        cp_async16(S + 2*A_BUF + bk2 * BSTP + bc4,                                  \
                   Whg + (size_t)((t) * 8 + bk2) * N + bc4);                        \
        cp_async16(S + 2*A_BUF + B_BUF + bk2 * BSTP + bc4,                          \
                   Wlg + (size_t)((t) * 8 + bk2) * N + bc4);                        \
        asm volatile("cp.async.commit_group;\n");                                   \
    }

    ISSUE(0);
    ISSUE(1);

    for (int t = 0; t < nt; t++) {
        if (t < nt - 1) asm volatile("cp.async.wait_group 1;\n");
        else            asm volatile("cp.async.wait_group 0;\n");
        __syncthreads();
        if (t + 2 < nt) ISSUE(t + 2);

        const uint32_t* S   = dynsm + (t % 3) * STG_U32;
        const uint32_t* sAh = S;
        const uint32_t* sAl = S + A_BUF;
        const uint32_t* sBh = S + 2*A_BUF;
        const uint32_t* sBl = S + 2*A_BUF + B_BUF;

        uint32_t ah[4][4], al[4][4], bh[4][2], bl[4][2];
        const int r0 = wm + (lane >> 2);
        const int k2 = lane & 3;
        #pragma unroll
        for (int mi = 0; mi < 4; mi++) {
            const int rb = (r0 + mi * 16) * ASTP;
            ah[mi][0] = sAh[rb + k2];
            ah[mi][1] = sAh[rb + 8 * ASTP + k2];
            ah[mi][2] = sAh[rb + 4 + k2];
            ah[mi][3] = sAh[rb + 8 * ASTP + 4 + k2];
            al[mi][0] = sAl[rb + k2];
            al[mi][1] = sAl[rb + 8 * ASTP + k2];
            al[mi][2] = sAl[rb + 4 + k2];
            al[mi][3] = sAl[rb + 8 * ASTP + 4 + k2];
        }
        const int bn0 = wn + (lane >> 2);
        #pragma unroll
        for (int ni = 0; ni < 4; ni++) {
            bh[ni][0] = sBh[k2 * BSTP + bn0 + ni * 8];
            bh[ni][1] = sBh[(k2 + 4) * BSTP + bn0 + ni * 8];
            bl[ni][0] = sBl[k2 * BSTP + bn0 + ni * 8];
            bl[ni][1] = sBl[(k2 + 4) * BSTP + bn0 + ni * 8];
        }
        #pragma unroll
        for (int mi = 0; mi < 4; mi++)
            #pragma unroll
            for (int ni = 0; ni < 4; ni++) {
                mma_bf16(c[mi][ni], al[mi], bh[ni]);
                mma_bf16(c[mi][ni], ah[mi], bl[ni]);
                mma_bf16(c[mi][ni], ah[mi], bh[ni]);
            }
    }
#undef ISSUE

    // epilogue
    const bool lnepi = (ecs != nullptr);
    #pragma unroll
    for (int mi = 0; mi < 4; mi++) {
        const int r0 = bm + wm + mi * 16 + (lane >> 2);
        #pragma unroll
        for (int ni = 0; ni < 4; ni++) {
            const int cc = bn + wn + ni * 8 + 2 * (lane & 3);
            float b0 = 0.f, b1 = 0.f;
            if (bias) { b0 = bias[cc]; b1 = bias[cc + 1]; }
            float cs0 = 0.f, cs1 = 0.f, u0 = 0.f, u1 = 0.f;
            if (lnepi) { cs0 = ecs[cc]; cs1 = ecs[cc + 1]; u0 = eu[cc]; u1 = eu[cc + 1]; }
            #pragma unroll
            for (int half = 0; half < 2; half++) {
                const int r = r0 + half * 8;
                const size_t ro = (size_t)r * N + cc;
                float v0, v1;
                if (lnepi) {
                    float m = emu[r], sgn = ers[r];
                    v0 = sgn * (c[mi][ni][half * 2 + 0] - m * cs0) + u0;
                    v1 = sgn * (c[mi][ni][half * 2 + 1] - m * cs1) + u1;
                } else {
                    v0 = c[mi][ni][half * 2 + 0] + b0;
                    v1 = c[mi][ni][half * 2 + 1] + b1;
                }
                if (act) {
                    v0 = v0 / (1.0f + expf(-v0));
                    v1 = v1 / (1.0f + expf(-v1));
                }
                if (add1) { float2 a = *(const float2*)(add1 + ro); v0 += a.x; v1 += a.y; }
                if (add2) { float2 a = *(const float2*)(add2 + ro); v0 += a.x; v1 += a.y; }
                if (C) { float2 o; o.x = v0; o.y = v1; *(float2*)(C + ro) = o; }
                if (Ch) {
                    uint32_t h, l;
                    split_pair(v0, v1, h, l);
                    size_t po = (size_t)r * (N >> 1) + (cc >> 1);
                    Ch[po] = h; Cl[po] = l;
                }
            }
        }
    }
}

// ---------------- pack all weights -> [K/2][N] bf16 hi/lo ----------------
__global__ void pack_w_kernel(
    const float* __restrict__ Wp, const float* __restrict__ Wlin,
    const float* __restrict__ Wval, const float* __restrict__ Wout,
    const float* __restrict__ Wm1, const float* __restrict__ Wm2,
    const float* __restrict__ ln1g, const float* __restrict__ ln2g)
{
    int idx = blockIdx.x * blockDim.x + threadIdx.x;
    if (idx >= WTOT) return;
    const float* W; const float* gains = nullptr; int N, off;
    if (idx < 8192) { W = Wp; N = DD; off = idx; }
    else {
        int j = idx - 8192, l = j / WSEG, u = j % WSEG;
        if (u < 8192)       { W = Wlin + (size_t)l*DD*DD; gains = ln1g + l*DD; N = DD; off = u; }
        else if (u < 16384) { W = Wval + (size_t)l*DD*DD; gains = ln1g + l*DD; N = DD; off = u - 8192; }
        else if (u < 24576) { W = Wout + (size_t)l*DD*DD; N = DD; off = u - 16384; }
        else if (u < 57344) { W = Wm1  + (size_t)l*DD*D4; gains = ln2g + l*DD; N = D4; off = u - 24576; }
        else                { W = Wm2  + (size_t)l*D4*DD; N = DD; off = u - 57344; }
    }
    int k2 = off / N, n = off - k2 * N;
    float w0 = W[(size_t)(2 * k2) * N + n];
    float w1 = W[(size_t)(2 * k2 + 1) * N + n];
    if (gains) { w0 *= gains[2 * k2]; w1 *= gains[2 * k2 + 1]; }
    uint32_t h, l;
    split_pair(w0, w1, h, l);
    g_WH[idx] = h; g_WL[idx] = l;
}

// ---------------- pack activation fp32 -> bf16 hi/lo pairs ----------------
__global__ void pack_act_kernel(const float* __restrict__ X, int n2,
                                uint32_t* __restrict__ ph, uint32_t* __restrict__ pl)
{
    int idx = blockIdx.x * blockDim.x + threadIdx.x;
    if (idx >= n2) return;
    float2 x = ((const float2*)X)[idx];
    uint32_t h, l;
    split_pair(x.x, x.y, h, l);
    ph[idx] = h; pl[idx] = l;
}

// ---------------- LN epilogue vectors: cs = colsum(gW), u = b@W (+extra) ----
__global__ void prep_vec_kernel(
    const float* __restrict__ Wlin, const float* __restrict__ Wval,
    const float* __restrict__ Wm1,
    const float* __restrict__ ln1g, const float* __restrict__ ln1b,
    const float* __restrict__ ln2g, const float* __restrict__ ln2b,
    const float* __restrict__ bm1)
{
    int l = blockIdx.x / 3, ty = blockIdx.x % 3;
    const float *W, *g, *b, *extra = nullptr; int N; float *cs, *u;
    int lb = l * VECL;
    if (ty == 0)      { W = Wlin + (size_t)l*DD*DD; g = ln1g + l*DD; b = ln1b + l*DD; N = DD; cs = g_CS + lb;      u = g_US + lb; }
    else if (ty == 1) { W = Wval + (size_t)l*DD*DD; g = ln1g + l*DD; b = ln1b + l*DD; N = DD; cs = g_CS + lb + DD; u = g_US + lb + DD; }
    else              { W = Wm1  + (size_t)l*DD*D4; g = ln2g + l*DD; b = ln2b + l*DD; N = D4; extra = bm1 + l*D4;
                        cs = g_CS + lb + 2*DD; u = g_US + lb + 2*DD; }
    for (int n = threadIdx.x; n < N; n += blockDim.x) {
        float s = 0.f, uu = 0.f;
        for (int k = 0; k < DD; k++) {
            float w = W[(size_t)k * N + n];
            s += g[k] * w; uu += b[k] * w;
        }
        cs[n] = s; u[n] = uu + (extra ? extra[n] : 0.f);
    }
}

// ---------------- LN stats only (warp per row of 128) ----------------
__global__ void ln_stats_kernel(const float* __restrict__ X,
                                float* __restrict__ mu, float* __restrict__ rs)
{
    int r = blockIdx.x * (blockDim.x >> 5) + (threadIdx.x >> 5);
    if (r >= NROWS) return;
    int lane = threadIdx.x & 31;
    const float* x = X + (size_t)r * DD;
    float s = 0.f, ss = 0.f;
    #pragma unroll
    for (int q = 0; q < 4; q++) { float v = x[lane + 32*q]; s += v; ss += v*v; }
    #pragma unroll
    for (int o = 16; o; o >>= 1) {
        s  += __shfl_xor_sync(0xffffffffu, s,  o);
        ss += __shfl_xor_sync(0xffffffffu, ss, o);
    }
    float m   = s  * (1.f/128.f);
    float var = ss * (1.f/128.f) - m * m;
    if (lane == 0) { mu[r] = m; rs[r] = rsqrtf(var + 1e-5f); }
}

// ---------------- NodeGate: U<-U*g in place; packed gated-U; LN2 stats ------
__global__ void gate_kernel(float* __restrict__ U,
    const float* __restrict__ g1w, const float* __restrict__ g1b,
    const float* __restrict__ g2w, const float* __restrict__ g2bp,
    uint32_t* __restrict__ UgH, uint32_t* __restrict__ UgL,
    float* __restrict__ mu2, float* __restrict__ rs2)
{
    int r = blockIdx.x * (blockDim.x >> 5) + (threadIdx.x >> 5);
    if (r >= NROWS) return;
    int lane = threadIdx.x & 31;
    float4* u4 = (float4*)(U + (size_t)r * DD);
    float4 x = u4[lane];
    float s  = x.x + x.y + x.z + x.w;
    float ss = x.x*x.x + x.y*x.y + x.z*x.z + x.w*x.w;
    #pragma unroll
    for (int o = 16; o; o >>= 1) {
        s  += __shfl_xor_sync(0xffffffffu, s,  o);
        ss += __shfl_xor_sync(0xffffffffu, ss, o);
    }
    float m   = s  * (1.f/128.f);
    float var = ss * (1.f/128.f) - m * m;
    float4 w1 = *(const float4*)(g1w + lane*4);
    float4 b1 = *(const float4*)(g1b + lane*4);
    float4 w2 = *(const float4*)(g2w + lane*4);
    float acc = 0.f;
    {
        float t0 = m*w1.x + b1.x; acc += (t0/(1.f+expf(-t0)))*w2.x;
        float t1 = m*w1.y + b1.y; acc += (t1/(1.f+expf(-t1)))*w2.y;
        float t2 = m*w1.z + b1.z; acc += (t2/(1.f+expf(-t2)))*w2.z;
        float t3 = m*w1.w + b1.w; acc += (t3/(1.f+expf(-t3)))*w2.w;
    }
    #pragma unroll
    for (int o = 16; o; o >>= 1) acc += __shfl_xor_sync(0xffffffffu, acc, o);
    float gate = 1.f / (1.f + expf(-(acc + g2bp[0])));
    float4 vg; vg.x = x.x*gate; vg.y = x.y*gate; vg.z = x.z*gate; vg.w = x.w*gate;
    u4[lane] = vg;
    uint32_t h, l;
    size_t po = (size_t)r * 64 + lane * 2;
    split_pair(vg.x, vg.y, h, l); UgH[po] = h;     UgL[po] = l;
    split_pair(vg.z, vg.w, h, l); UgH[po + 1] = h; UgL[po + 1] = l;
    if (lane == 0) {
        mu2[r] = m * gate;
        rs2[r] = rsqrtf(var * gate * gate + 1e-5f);
    }
}

// ---------------- Hmix = A @ LN1(Z) ----------------
__global__ __launch_bounds__(256) void hmix_kernel(const float* __restrict__ A,
    const float* __restrict__ Z,
    const float* __restrict__ mu, const float* __restrict__ rs,
    const float* __restrict__ lng, const float* __restrict__ lnb,
    float* __restrict__ Hmix)
{
    __shared__ float sA[NN*NN];
    __shared__ float sH[NN*DD];
    int bt = blockIdx.x;
    for (int t = threadIdx.x; t < NN*NN; t += blockDim.x) sA[t] = A[t];
    const float* Zb = Z + (size_t)bt * NN * DD;
    const int rbase = bt * NN;
    for (int t = threadIdx.x; t < NN*DD; t += blockDim.x) {
        int j = t >> 7, d = t & 127;
        sH[t] = (Zb[t] - mu[rbase + j]) * rs[rbase + j] * lng[d] + lnb[d];
    }
    __syncthreads();
    int d = threadIdx.x & 127;
    for (int i = threadIdx.x >> 7; i < NN; i += 2) {
        float acc = 0.f;
        #pragma unroll 8
        for (int j = 0; j < NN; j++) acc += sA[i*NN + j] * sH[j*DD + d];
        Hmix[((size_t)bt * NN + i) * DD + d] = acc;
    }
}

// ---------------- blended adjacency A ----------------
__global__ void adj_kernel(const float* __restrict__ A0, const float* __restrict__ P,
                           const float* __restrict__ Qm, const float* __restrict__ alphap,
                           float* __restrict__ A)
{
    int i = blockIdx.x, j = threadIdx.x;
    float a0 = A0[i*NN + j];
    float dot = 0.f;
    #pragma unroll
    for (int r = 0; r < 8; r++) dot += P[i*8 + r] * Qm[j*8 + r];
    float sp = (dot > 20.f) ? dot : log1pf(expf(dot));
    float ad = (a0 > 0.f) ? sp : 0.f;
    float a  = a0 * (1.f + alphap[0] * ad);
    __shared__ float sbuf[NN];
    sbuf[j] = a;
    __syncthreads();
    for (int st = 32; st >= 1; st >>= 1) {
        if (j < st) sbuf[j] += sbuf[j + st];
        __syncthreads();
    }
    A[i*NN + j] = a / (sbuf[0] + 1e-8f);
}

// ---------------- edge prep ----------------
__global__ void rowptr_kernel(const int* __restrict__ src, int E, int* __restrict__ rowptr)
{
    int t = threadIdx.x;
    if (t > NN) return;
    int lo = 0, hi = E;
    while (lo < hi) { int mid = (lo + hi) >> 1; if (src[mid] < t) lo = mid + 1; else hi = mid; }
    rowptr[t] = lo;
}

__global__ void edge_kernel(const int* __restrict__ src, const int* __restrict__ dst,
                            const float* __restrict__ A0, int E, float* __restrict__ logA0)
{
    int e = blockIdx.x * blockDim.x + threadIdx.x;
    if (e < E) logA0[e] = logf(A0[src[e]*NN + dst[e]] + 1e-8f);
}

// ---------------- GATv2: block = bt; warp owns (head, node); writes packed Y
#define AST2 129
__global__ __launch_bounds__(256) void attn_kernel(
    const float* __restrict__ Xq, const float* __restrict__ Xv,
    const float* __restrict__ a_att_l,
    const int* __restrict__ dstidx,
    const float* __restrict__ logA0, int E,
    uint32_t* __restrict__ Yh, uint32_t* __restrict__ Yl)
{
    extern __shared__ float smem[];
    float* sXq  = smem;
    float* sXv  = sXq + NN * AST2;
    float* slog = sXv + NN * AST2;
    int*   sdst = (int*)(slog + MAXE);
    float* sexp = (float*)(sdst + MAXE);
    float* sa   = sexp + 8 * NN;

    const int bt   = blockIdx.x;
    const int tid  = threadIdx.x;
    const int wid  = tid >> 5;
    const int lane = tid & 31;
    const int h    = wid & 3;
    const int half = wid >> 2;
    const size_t base = (size_t)bt * NN * DD;

    for (int idx = tid; idx < NN * DD; idx += 256) {
        int r = idx >> 7, d = idx & 127;
        sXq[r * AST2 + d] = Xq[base + idx];
        sXv[r * AST2 + d] = Xv[base + idx];
    }
    for (int k = tid; k < E; k += 256) {
        sdst[k] = dstidx[k];
        slog[k] = logA0[k];
    }
    if (tid < HH * DHH) sa[tid] = a_att_l[tid];
    __syncthreads();

    float* myexp = sexp + wid * NN;

    for (int i = half; i < NN; i += 2) {
        const int e0  = g_rowptr[i];
        const int deg = g_rowptr[i + 1] - e0;
        const float* qrow = &sXq[i * AST2 + h * DHH];

        float vmax = -1e30f;
        for (int kb = 0; kb < deg; kb += 32) {
            const int k = kb + lane;
            const bool ok = (k < deg);
            const int j = ok ? sdst[e0 + k] : 0;
            const float* jrow = &sXq[j * AST2 + h * DHH];
            float acc = 0.f;
            #pragma unroll
            for (int d = 0; d < DHH; d++) {
                float x = qrow[d] + jrow[d];
                x = (x > 0.f) ? x : 0.2f * x;
                acc = fmaf(x, sa[h * DHH + d], acc);
            }
            float v = ok ? (acc + slog[e0 + k]) : -1e30f;
            if (ok) myexp[k] = v;
            vmax = fmaxf(vmax, v);
        }
        #pragma unroll
        for (int o = 16; o; o >>= 1) vmax = fmaxf(vmax, __shfl_xor_sync(0xffffffffu, vmax, o));
        __syncwarp();

        float den = 0.f;
        for (int kb = 0; kb < deg; kb += 32) {
            const int k = kb + lane;
            if (k < deg) {
                float ev = expf(myexp[k] - vmax);
                myexp[k] = ev;
                den += ev;
            }
        }
        #pragma unroll
        for (int o = 16; o; o >>= 1) den += __shfl_xor_sync(0xffffffffu, den, o);
        __syncwarp();
        const float inv = 1.f / den;

        float y = 0.f;
        for (int k = 0; k < deg; k++) {
            const int j = sdst[e0 + k];
            y = fmaf(myexp[k], sXv[j * AST2 + h * DHH + lane], y);
        }
        float yf = y * inv;
        float yp = __shfl_down_sync(0xffffffffu, yf, 1);
        if (!(lane & 1)) {
            uint32_t hh, ll;
            split_pair(yf, yp, hh, ll);
            size_t po = (size_t)bt * NN * 64 + (size_t)i * 64 + h * 16 + (lane >> 1);
            Yh[po] = hh; Yl[po] = ll;
        }
        __syncwarp();
    }
}
#define ATTN_SMEM ((2 * NN * AST2 + 2 * MAXE + 8 * NN + 128) * 4)

// ---------------- outputs ----------------
__global__ void copy_kernel(const float* __restrict__ src, float* __restrict__ dst, int n4)
{
    int i = blockIdx.x * blockDim.x + threadIdx.x;
    if (i < n4) ((float4*)dst)[i] = ((const float4*)src)[i];
}

__global__ void s_kernel(const float* __restrict__ Z, float* __restrict__ S)
{
    int idx = blockIdx.x * blockDim.x + threadIdx.x;
    if (idx >= NBT * DD) return;
    int bt = idx >> 7, d = idx & 127;
    float acc = 0.f;
    for (int n = 0; n < NN; n++) acc += Z[(((size_t)bt * NN) + n) * DD + d];
    S[idx] = acc * (1.f / (float)NN);
}

__global__ void fill0_kernel(float* __restrict__ p, int n)
{
    int i = blockIdx.x * blockDim.x + threadIdx.x;
    if (i < n) p[i] = 0.f;
}

// ---------------- host driver ----------------
static inline void gemm(const uint32_t* Ah, const uint32_t* Al, int wOff,
                        float* C, uint32_t* Ch, uint32_t* Cl,
                        int M, int K, int N,
                        const float* bias, const float* add1, const float* add2, int act,
                        const float* emu = nullptr, const float* ers = nullptr,
                        const float* ecs = nullptr, const float* eu = nullptr)
{
    dim3 g(N / 128, M / 128);
    hgemm_kernel<<<g, 256, GEMM_SMEM>>>(Ah, Al, wOff, C, Ch, Cl, M, K, N,
                                        bias, add1, add2, act, emu, ers, ecs, eu);
}

extern "C" void kernel_launch(void* const* d_in, const int* in_sizes, int n_in,
                              void* d_out, int out_size)
{
    const float* X     = (const float*)d_in[0];
    const float* Wp    = (const float*)d_in[1];
    const float* bp    = (const float*)d_in[2];
    const float* P     = (const float*)d_in[3];
    const float* Qm    = (const float*)d_in[4];
    const float* alpha = (const float*)d_in[5];
    const float* ln1g  = (const float*)d_in[6];
    const float* ln1b  = (const float*)d_in[7];
    const float* Wlin  = (const float*)d_in[8];
    const float* Wval  = (const float*)d_in[9];
    const float* a_att = (const float*)d_in[10];
    const float* Wout  = (const float*)d_in[11];
    const float* g1w   = (const float*)d_in[12];
    const float* g1b   = (const float*)d_in[13];
    const float* g2w   = (const float*)d_in[14];
    const float* g2b   = (const float*)d_in[15];
    const float* ln2g  = (const float*)d_in[16];
    const float* ln2b  = (const float*)d_in[17];
    const float* Wm1   = (const float*)d_in[18];
    const float* bm1   = (const float*)d_in[19];
    const float* Wm2   = (const float*)d_in[20];
    const float* bm2   = (const float*)d_in[21];
    const float* A0    = (const float*)d_in[22];
    const int*   srcI  = (const int*)d_in[24];
    const int*   dstI  = (const int*)d_in[25];
    int E = in_sizes[24];
    float* out = (float*)d_out;

    float *Z, *Hmix, *Xq, *Xv, *U, *A, *logA0;
    float *mu1, *rs1, *mu2, *rs2, *CS, *US;
    uint32_t *XH, *XL, *ZH, *ZL, *YH, *YL, *UgH, *UgL, *M1H, *M1L;
    int* rowptr;
    cudaGetSymbolAddress((void**)&Z,     g_Z);
    cudaGetSymbolAddress((void**)&Hmix,  g_Hmix);
    cudaGetSymbolAddress((void**)&Xq,    g_Xq);
    cudaGetSymbolAddress((void**)&Xv,    g_Xv);
    cudaGetSymbolAddress((void**)&U,     g_U);
    cudaGetSymbolAddress((void**)&A,     g_A);
    cudaGetSymbolAddress((void**)&logA0, g_logA0);
    cudaGetSymbolAddress((void**)&rowptr, g_rowptr);
    cudaGetSymbolAddress((void**)&mu1,   g_mu1);
    cudaGetSymbolAddress((void**)&rs1,   g_rs1);
    cudaGetSymbolAddress((void**)&mu2,   g_mu2);
    cudaGetSymbolAddress((void**)&rs2,   g_rs2);
    cudaGetSymbolAddress((void**)&CS,    g_CS);
    cudaGetSymbolAddress((void**)&US,    g_US);
    cudaGetSymbolAddress((void**)&XH,    g_XH);
    cudaGetSymbolAddress((void**)&XL,    g_XL);
    cudaGetSymbolAddress((void**)&ZH,    g_ZH);
    cudaGetSymbolAddress((void**)&ZL,    g_ZL);
    cudaGetSymbolAddress((void**)&YH,    g_YH);
    cudaGetSymbolAddress((void**)&YL,    g_YL);
    cudaGetSymbolAddress((void**)&UgH,   g_UgH);
    cudaGetSymbolAddress((void**)&UgL,   g_UgL);
    cudaGetSymbolAddress((void**)&M1H,   g_M1H);
    cudaGetSymbolAddress((void**)&M1L,   g_M1L);

    cudaFuncSetAttribute(attn_kernel,  cudaFuncAttributeMaxDynamicSharedMemorySize, ATTN_SMEM);
    cudaFuncSetAttribute(hgemm_kernel, cudaFuncAttributeMaxDynamicSharedMemorySize, GEMM_SMEM);

    const int ZN = NROWS * DD;
    const int SN = NBT * DD;
    const int AN = NN * NN;
    float* Zfinal = (out_size >= ZN) ? out : Z;

    // --- setup ---
    pack_w_kernel<<<(WTOT + 255) / 256, 256>>>(Wp, Wlin, Wval, Wout, Wm1, Wm2, ln1g, ln2g);
    prep_vec_kernel<<<LL * 3, 256>>>(Wlin, Wval, Wm1, ln1g, ln1b, ln2g, ln2b, bm1);
    pack_act_kernel<<<(NROWS * 64 + 255) / 256, 256>>>(X, NROWS * 64, XH, XL);
    adj_kernel<<<NN, NN>>>(A0, P, Qm, alpha, A);
    rowptr_kernel<<<1, 128>>>(srcI, E, rowptr);
    edge_kernel<<<(E + 127) / 128, 128>>>(srcI, dstI, A0, E, logA0);
    // Z = X@Wp + bp  (also emits packed Z)
    gemm(XH, XL, WOFF_WP, Z, ZH, ZL, NROWS, DD, DD, bp, nullptr, nullptr, 0);

    const int LN_BLOCKS = NROWS / 8;

    for (int l = 0; l < LL; l++) {
        const float* l1g = ln1g + l * DD, *l1b = ln1b + l * DD;
        const float* csq = CS + l * VECL,        *uq = US + l * VECL;
        const float* csv = CS + l * VECL + DD,   *uv = US + l * VECL + DD;
        const float* csm = CS + l * VECL + 2*DD, *um = US + l * VECL + 2*DD;

        ln_stats_kernel<<<LN_BLOCKS, 256>>>(Z, mu1, rs1);

        gemm(ZH, ZL, WOFF_LIN(l), Xq, nullptr, nullptr, NROWS, DD, DD,
             nullptr, nullptr, nullptr, 0, mu1, rs1, csq, uq);
        gemm(ZH, ZL, WOFF_VAL(l), Xv, nullptr, nullptr, NROWS, DD, DD,
             nullptr, nullptr, nullptr, 0, mu1, rs1, csv, uv);
        hmix_kernel<<<NBT, 256>>>(A, Z, mu1, rs1, l1g, l1b, Hmix);

        attn_kernel<<<NBT, 256, ATTN_SMEM>>>(Xq, Xv, a_att + l * HH * DHH,
                                             dstI, logA0, E, YH, YL);

        // U = Y@Wout + Z + Hmix
        gemm(YH, YL, WOFF_OUT(l), U, nullptr, nullptr, NROWS, DD, DD,
             nullptr, Z, Hmix, 0);

        // gate in place; packed gated-U; LN2 stats
        gate_kernel<<<LN_BLOCKS, 256>>>(U, g1w + l * DD, g1b + l * DD,
                                        g2w + l * DD, g2b + l, UgH, UgL, mu2, rs2);

        // MLP: M1(packed only) = silu(LN2(Ug)@Wm1 + bm1); Z = M1@Wm2 + bm2 + Ug
        gemm(UgH, UgL, WOFF_M1(l), nullptr, M1H, M1L, NROWS, DD, D4,
             nullptr, nullptr, nullptr, 1, mu2, rs2, csm, um);
        float* Ztgt = (l == LL - 1) ? Zfinal : Z;
        gemm(M1H, M1L, WOFF_M2(l), Ztgt, ZH, ZL, NROWS, D4, DD,
             bm2 + l * DD, U, nullptr, 0);
    }

    // --- outputs: [Zout | S | A] ---
    if (out_size >= ZN && Zfinal != out)
        copy_kernel<<<(ZN / 4 + 255) / 256, 256>>>(Z, out, ZN / 4);
    if (out_size >= ZN + SN)
        s_kernel<<<(SN + 255) / 256, 256>>>(Zfinal, out + ZN);
    if (out_size >= ZN + SN + AN)
        copy_kernel<<<(AN / 4 + 255) / 256, 256>>>(A, out + ZN + SN, AN / 4);
    int tail = out_size - (ZN + SN + AN);
    if (tail > 0)
        fill0_kernel<<<(tail + 255) / 256, 256>>>(out + ZN + SN + AN, tail);
}

// round 13
// speedup vs baseline: 1.1827x; 1.1827x over previous
#include <cuda_runtime.h>
#include <math.h>
#include <stdint.h>

// ---------------- problem constants ----------------
#define NBT 512
#define NN 64
#define DD 128
#define HH 4
#define DHH 32
#define LL 3
#define D4 512
#define NROWS (NBT*NN)
#define MAXE 4096

// packed weights (u32 units; [K/2][N] k2-major), raw values (LN applied in-kernel)
#define WOFF_WP   0
#define WSEG      90112
#define WOFF_LIN(l)  (8192 + (l)*WSEG)
#define WOFF_VAL(l)  (8192 + (l)*WSEG + 8192)
#define WOFF_OUT(l)  (8192 + (l)*WSEG + 16384)
#define WOFF_M1(l)   (8192 + (l)*WSEG + 24576)
#define WOFF_M2(l)   (8192 + (l)*WSEG + 57344)
#define WTOT      (8192 + LL*WSEG)

// ---------------- device globals ----------------
__device__ float g_Z[NROWS*DD];          // fallback Z output
__device__ float g_A[NN*NN];
__device__ float g_logA0[MAXE];
__device__ int   g_rowptr[NN+1];
__device__ uint32_t g_WH[WTOT], g_WL[WTOT];
__device__ uint32_t g_AJH[NN*32], g_AJL[NN*32];   // adjacency packed pairs along j

// ---------------- helpers ----------------
__device__ __forceinline__ uint32_t smem_u32(const void* p) {
    uint32_t a;
    asm("{ .reg .u64 t; cvta.to.shared.u64 t, %1; cvt.u32.u64 %0, t; }" : "=r"(a) : "l"(p));
    return a;
}
__device__ __forceinline__ void cp_async16(void* smem, const void* gmem) {
    unsigned sa = smem_u32(smem);
    asm volatile("cp.async.cg.shared.global [%0], [%1], 16;\n" :: "r"(sa), "l"(gmem));
}
__device__ __forceinline__ uint32_t pack_bf16x2(float x0, float x1) {
    uint32_t r;
    asm("cvt.rn.bf16x2.f32 %0, %1, %2;" : "=r"(r) : "f"(x1), "f"(x0));
    return r;
}
__device__ __forceinline__ void split_pair(float x0, float x1, uint32_t& h2, uint32_t& l2) {
    h2 = pack_bf16x2(x0, x1);
    float h0 = __uint_as_float(h2 << 16);
    float h1 = __uint_as_float(h2 & 0xffff0000u);
    l2 = pack_bf16x2(x0 - h0, x1 - h1);
}
__device__ __forceinline__ void mma_bf16(float* c, const uint32_t* a, const uint32_t* b) {
    asm volatile("mma.sync.aligned.m16n8k16.row.col.f32.bf16.bf16.f32 "
        "{%0,%1,%2,%3}, {%4,%5,%6,%7}, {%8,%9}, {%0,%1,%2,%3};"
        : "+f"(c[0]), "+f"(c[1]), "+f"(c[2]), "+f"(c[3])
        : "r"(a[0]), "r"(a[1]), "r"(a[2]), "r"(a[3]), "r"(b[0]), "r"(b[1]));
}

// ---------------- smem layout (4B units) ----------------
#define SM_Z    0
#define SM_U    8192
#define SM_W1   16384
#define SM_XQ   24576      // 64*129
#define SM_XV   32832      // 64*129
#define SM_PH   41088      // 64*68 u32
#define SM_PL   45440
#define SM_WST  49792      // 3*2176 u32
#define SM_EXP  56320      // 8*64
#define SM_DSTW 56832      // 8*64 int
#define SM_SA   57344      // 128
#define SM_TOT  57472      // *4 = 229,888 B
#define XST 129
#define PST 68

// ---------------- block-level gemm: M=64, N=128, A resident, B streamed ------
__device__ __forceinline__ void gemm_stream(
    const uint32_t* __restrict__ Ah, const uint32_t* __restrict__ Al,
    const uint32_t* __restrict__ Bh, const uint32_t* __restrict__ Bl,
    int bst, int ktiles, uint32_t* wst,
    float (&acc)[2][4][4], int tid, int lane, int wm, int wn)
{
    const int bk2 = tid >> 5, bc4 = (tid & 31) * 4;
    __syncthreads();   // prior phase writes visible; wst free
#define GISSUE(t) { \
        uint32_t* S_ = wst + ((t) % 3) * 2176; \
        cp_async16(S_ + bk2*136 + bc4,        Bh + (size_t)((t)*8 + bk2)*bst + bc4); \
        cp_async16(S_ + 1088 + bk2*136 + bc4, Bl + (size_t)((t)*8 + bk2)*bst + bc4); \
        asm volatile("cp.async.commit_group;\n"); }
    GISSUE(0); GISSUE(1);
    for (int t = 0; t < ktiles; t++) {
        if (t < ktiles - 1) asm volatile("cp.async.wait_group 1;\n");
        else                asm volatile("cp.async.wait_group 0;\n");
        __syncthreads();
        if (t + 2 < ktiles) GISSUE(t + 2);
        const uint32_t* Sh = wst + (t % 3) * 2176;
        const uint32_t* Sl = Sh + 1088;
        const int r0 = wm + (lane >> 2);
        const int ka = t * 8 + (lane & 3);
        const int kb_ = lane & 3;
        uint32_t ah[2][4], al2[2][4], bh[4][2], bl[4][2];
        #pragma unroll
        for (int mi = 0; mi < 2; mi++) {
            const int rb = (r0 + mi * 16) * PST;
            ah[mi][0]  = Ah[rb + ka];
            ah[mi][1]  = Ah[rb + 8 * PST + ka];
            ah[mi][2]  = Ah[rb + ka + 4];
            ah[mi][3]  = Ah[rb + 8 * PST + ka + 4];
            al2[mi][0] = Al[rb + ka];
            al2[mi][1] = Al[rb + 8 * PST + ka];
            al2[mi][2] = Al[rb + ka + 4];
            al2[mi][3] = Al[rb + 8 * PST + ka + 4];
        }
        const int bn0 = wn + (lane >> 2);
        #pragma unroll
        for (int ni = 0; ni < 4; ni++) {
            bh[ni][0] = Sh[kb_*136 + bn0 + ni*8];
            bh[ni][1] = Sh[(kb_+4)*136 + bn0 + ni*8];
            bl[ni][0] = Sl[kb_*136 + bn0 + ni*8];
            bl[ni][1] = Sl[(kb_+4)*136 + bn0 + ni*8];
        }
        #pragma unroll
        for (int mi = 0; mi < 2; mi++)
            #pragma unroll
            for (int ni = 0; ni < 4; ni++) {
                mma_bf16(acc[mi][ni], al2[mi], bh[ni]);
                mma_bf16(acc[mi][ni], ah[mi],  bl[ni]);
                mma_bf16(acc[mi][ni], ah[mi],  bh[ni]);
            }
    }
#undef GISSUE
}

// ---------------- block gemm with BOTH operands resident (hmix) --------------
__device__ __forceinline__ void gemm_resident(
    const uint32_t* __restrict__ Ah, const uint32_t* __restrict__ Al,
    const uint32_t* __restrict__ BhR, const uint32_t* __restrict__ BlR,
    int ktiles, float (&acc)[2][4][4], int lane, int wm, int wn)
{
    for (int t = 0; t < ktiles; t++) {
        const int r0 = wm + (lane >> 2);
        const int ka = t * 8 + (lane & 3);
        uint32_t ah[2][4], al2[2][4], bh[4][2], bl[4][2];
        #pragma unroll
        for (int mi = 0; mi < 2; mi++) {
            const int rb = (r0 + mi * 16) * PST;
            ah[mi][0]  = Ah[rb + ka];
            ah[mi][1]  = Ah[rb + 8 * PST + ka];
            ah[mi][2]  = Ah[rb + ka + 4];
            ah[mi][3]  = Ah[rb + 8 * PST + ka + 4];
            al2[mi][0] = Al[rb + ka];
            al2[mi][1] = Al[rb + 8 * PST + ka];
            al2[mi][2] = Al[rb + ka + 4];
            al2[mi][3] = Al[rb + 8 * PST + ka + 4];
        }
        const int bn0 = wn + (lane >> 2);
        #pragma unroll
        for (int ni = 0; ni < 4; ni++) {
            bh[ni][0] = BhR[ka*136 + bn0 + ni*8];
            bh[ni][1] = BhR[(ka+4)*136 + bn0 + ni*8];
            bl[ni][0] = BlR[ka*136 + bn0 + ni*8];
            bl[ni][1] = BlR[(ka+4)*136 + bn0 + ni*8];
        }
        #pragma unroll
        for (int mi = 0; mi < 2; mi++)
            #pragma unroll
            for (int ni = 0; ni < 4; ni++) {
                mma_bf16(acc[mi][ni], al2[mi], bh[ni]);
                mma_bf16(acc[mi][ni], ah[mi],  bl[ni]);
                mma_bf16(acc[mi][ni], ah[mi],  bh[ni]);
            }
    }
}

#define ZERO_ACC(a) { _Pragma("unroll") for (int mi_=0;mi_<2;mi_++) \
    _Pragma("unroll") for (int ni_=0;ni_<4;ni_++) \
    _Pragma("unroll") for (int q_=0;q_<4;q_++) (a)[mi_][ni_][q_] = 0.f; }

// ---------------- the fused per-bt kernel ----------------
extern __shared__ float smf[];
__global__ __launch_bounds__(256) void fused_kernel(
    const float* __restrict__ X, const float* __restrict__ bp,
    const float* __restrict__ ln1g, const float* __restrict__ ln1b,
    const float* __restrict__ a_att,
    const float* __restrict__ g1w, const float* __restrict__ g1b,
    const float* __restrict__ g2w, const float* __restrict__ g2b,
    const float* __restrict__ ln2g, const float* __restrict__ ln2b,
    const float* __restrict__ bm1, const float* __restrict__ bm2,
    const int* __restrict__ dstI,
    float* __restrict__ Zdst, float* __restrict__ Sdst)
{
    const int bt   = blockIdx.x;
    const int tid  = threadIdx.x;
    const int lane = tid & 31;
    const int wid  = tid >> 5;
    const int wm   = (wid & 1) * 32;
    const int wn   = (wid >> 1) * 32;

    float*    sZ  = smf + SM_Z;
    float*    sU  = smf + SM_U;
    float*    W1  = smf + SM_W1;
    float*    sXq = smf + SM_XQ;
    float*    sXv = smf + SM_XV;
    uint32_t* XQu = (uint32_t*)sXq;
    uint32_t* XVu = (uint32_t*)sXv;
    uint32_t* Ph  = (uint32_t*)(smf + SM_PH);
    uint32_t* Pl  = (uint32_t*)(smf + SM_PL);
    uint32_t* wst = (uint32_t*)(smf + SM_WST);
    float*    sexp  = smf + SM_EXP;
    int*      sdstW = (int*)(smf + SM_DSTW);
    float*    sa    = smf + SM_SA;

    // ---- input pack: X slab -> P ----
    {
        const float* Xb = X + (size_t)bt * NN * DD;
        for (int idx = tid; idx < 4096; idx += 256) {
            int r = idx >> 6, p = idx & 63;
            float2 x = *(const float2*)(Xb + r * 128 + 2 * p);
            uint32_t h, l;
            split_pair(x.x, x.y, h, l);
            Ph[r * PST + p] = h; Pl[r * PST + p] = l;
        }
    }
    // proj: sZ = X@Wp + bp
    {
        float acc[2][4][4]; ZERO_ACC(acc);
        gemm_stream(Ph, Pl, g_WH + WOFF_WP, g_WL + WOFF_WP, 128, 8, wst,
                    acc, tid, lane, wm, wn);
        #pragma unroll
        for (int mi = 0; mi < 2; mi++)
            #pragma unroll
            for (int ni = 0; ni < 4; ni++)
                #pragma unroll
                for (int hf = 0; hf < 2; hf++) {
                    int r = wm + mi*16 + hf*8 + (lane >> 2);
                    int c = wn + ni*8 + 2*(lane & 3);
                    sZ[r*128 + c]     = acc[mi][ni][hf*2+0] + bp[c];
                    sZ[r*128 + c + 1] = acc[mi][ni][hf*2+1] + bp[c+1];
                }
    }
    __syncthreads();

    for (int l = 0; l < LL; l++) {
        // ---- LN1 -> W1 ----
        {
            float ga[4], ba[4];
            #pragma unroll
            for (int q = 0; q < 4; q++) {
                ga[q] = ln1g[l*128 + lane + 32*q];
                ba[q] = ln1b[l*128 + lane + 32*q];
            }
            for (int q = 0; q < 8; q++) {
                int r = wid * 8 + q;
                const float* zr = sZ + r * 128;
                float v0 = zr[lane], v1 = zr[lane+32], v2 = zr[lane+64], v3 = zr[lane+96];
                float s = v0+v1+v2+v3, ss = v0*v0+v1*v1+v2*v2+v3*v3;
                #pragma unroll
                for (int o = 16; o; o >>= 1) {
                    s  += __shfl_xor_sync(0xffffffffu, s,  o);
                    ss += __shfl_xor_sync(0xffffffffu, ss, o);
                }
                float mu = s * (1.f/128.f);
                float rs = rsqrtf(ss * (1.f/128.f) - mu*mu + 1e-5f);
                float* hr = W1 + r * 128;
                hr[lane]    = (v0-mu)*rs*ga[0] + ba[0];
                hr[lane+32] = (v1-mu)*rs*ga[1] + ba[1];
                hr[lane+64] = (v2-mu)*rs*ga[2] + ba[2];
                hr[lane+96] = (v3-mu)*rs*ga[3] + ba[3];
            }
            if (tid < 128) sa[tid] = a_att[l*128 + tid];
        }
        __syncthreads();

        // ---- vertical pack Hn -> XQu/XVu; adjacency -> P ----
        for (int idx = tid; idx < 4096; idx += 256) {
            int j2 = idx >> 7, d = idx & 127;
            uint32_t h, lo;
            split_pair(W1[(2*j2)*128 + d], W1[(2*j2+1)*128 + d], h, lo);
            XQu[j2*136 + d] = h; XVu[j2*136 + d] = lo;
        }
        for (int idx = tid; idx < 2048; idx += 256) {
            int i = idx >> 5, j2 = idx & 31;
            Ph[i*PST + j2] = g_AJH[i*32 + j2];
            Pl[i*PST + j2] = g_AJL[i*32 + j2];
        }
        __syncthreads();

        // ---- hmix: sU = sZ + A@Hn ----
        {
            float acc[2][4][4]; ZERO_ACC(acc);
            gemm_resident(Ph, Pl, XQu, XVu, 4, acc, lane, wm, wn);
            #pragma unroll
            for (int mi = 0; mi < 2; mi++)
                #pragma unroll
                for (int ni = 0; ni < 4; ni++)
                    #pragma unroll
                    for (int hf = 0; hf < 2; hf++) {
                        int r = wm + mi*16 + hf*8 + (lane >> 2);
                        int c = wn + ni*8 + 2*(lane & 3);
                        sU[r*128 + c]     = sZ[r*128 + c]     + acc[mi][ni][hf*2+0];
                        sU[r*128 + c + 1] = sZ[r*128 + c + 1] + acc[mi][ni][hf*2+1];
                    }
        }
        __syncthreads();

        // ---- horizontal pack Hn -> P ----
        for (int idx = tid; idx < 4096; idx += 256) {
            int r = idx >> 6, p = idx & 63;
            uint32_t h, lo;
            split_pair(W1[r*128 + 2*p], W1[r*128 + 2*p + 1], h, lo);
            Ph[r*PST + p] = h; Pl[r*PST + p] = lo;
        }

        // ---- Xq / Xv gemms ----
        for (int qv = 0; qv < 2; qv++) {
            float acc[2][4][4]; ZERO_ACC(acc);
            int off = qv ? WOFF_VAL(l) : WOFF_LIN(l);
            gemm_stream(Ph, Pl, g_WH + off, g_WL + off, 128, 8, wst,
                        acc, tid, lane, wm, wn);
            float* dst = qv ? sXv : sXq;
            #pragma unroll
            for (int mi = 0; mi < 2; mi++)
                #pragma unroll
                for (int ni = 0; ni < 4; ni++)
                    #pragma unroll
                    for (int hf = 0; hf < 2; hf++) {
                        int r = wm + mi*16 + hf*8 + (lane >> 2);
                        int c = wn + ni*8 + 2*(lane & 3);
                        dst[r*XST + c]     = acc[mi][ni][hf*2+0];
                        dst[r*XST + c + 1] = acc[mi][ni][hf*2+1];
                    }
        }
        __syncthreads();

        // ---- attention: warp = (head h, parity); Y packed -> P ----
        {
            const int h    = wid & 3;
            const int half = wid >> 2;
            const float a  = sa[h*32 + lane];
            float* myexp = sexp + wid * 64;
            int*   mydst = sdstW + wid * 64;
            for (int i = half; i < NN; i += 2) {
                const int e0  = g_rowptr[i];
                const int deg = g_rowptr[i+1] - e0;
                const float* qrow = sXq + i*XST + h*32;
                float vmax = -1e30f;
                for (int kb = 0; kb < deg; kb += 32) {
                    const int k = kb + lane;
                    const bool ok = (k < deg);
                    const int j = ok ? dstI[e0 + k] : 0;
                    const float* jrow = sXq + j*XST + h*32;
                    float accd = 0.f;
                    #pragma unroll
                    for (int d = 0; d < 32; d++) {
                        float x = qrow[d] + jrow[d];
                        x = (x > 0.f) ? x : 0.2f * x;
                        accd = fmaf(x, sa[h*32 + d], accd);
                    }
                    float v = ok ? (accd + g_logA0[e0 + k]) : -1e30f;
                    if (ok) { myexp[k] = v; mydst[k] = j; }
                    vmax = fmaxf(vmax, v);
                }
                #pragma unroll
                for (int o = 16; o; o >>= 1)
                    vmax = fmaxf(vmax, __shfl_xor_sync(0xffffffffu, vmax, o));
                __syncwarp();
                float den = 0.f;
                for (int kb = 0; kb < deg; kb += 32) {
                    const int k = kb + lane;
                    if (k < deg) {
                        float ev = expf(myexp[k] - vmax);
                        myexp[k] = ev;
                        den += ev;
                    }
                }
                #pragma unroll
                for (int o = 16; o; o >>= 1) den += __shfl_xor_sync(0xffffffffu, den, o);
                __syncwarp();
                const float inv = 1.f / den;
                float y = 0.f;
                #pragma unroll 4
                for (int k = 0; k < deg; k++)
                    y = fmaf(myexp[k], sXv[mydst[k]*XST + h*32 + lane], y);
                float yf = y * inv;
                float yp = __shfl_down_sync(0xffffffffu, yf, 1);
                if (!(lane & 1)) {
                    uint32_t hh, ll;
                    split_pair(yf, yp, hh, ll);
                    Ph[i*PST + h*16 + (lane >> 1)] = hh;
                    Pl[i*PST + h*16 + (lane >> 1)] = ll;
                }
                __syncwarp();
            }
            (void)a;
        }

        // ---- Wout gemm: sU += Y@Wout ----
        {
            float acc[2][4][4]; ZERO_ACC(acc);
            gemm_stream(Ph, Pl, g_WH + WOFF_OUT(l), g_WL + WOFF_OUT(l), 128, 8, wst,
                        acc, tid, lane, wm, wn);
            #pragma unroll
            for (int mi = 0; mi < 2; mi++)
                #pragma unroll
                for (int ni = 0; ni < 4; ni++)
                    #pragma unroll
                    for (int hf = 0; hf < 2; hf++) {
                        int r = wm + mi*16 + hf*8 + (lane >> 2);
                        int c = wn + ni*8 + 2*(lane & 3);
                        sU[r*128 + c]     += acc[mi][ni][hf*2+0];
                        sU[r*128 + c + 1] += acc[mi][ni][hf*2+1];
                    }
        }
        __syncthreads();

        // ---- gate + LN2 -> sU gated (in place), W1 = LN2(sU) ----
        {
            float4 w1v = *(const float4*)(g1w + l*128 + lane*4);
            float4 b1v = *(const float4*)(g1b + l*128 + lane*4);
            float4 w2v = *(const float4*)(g2w + l*128 + lane*4);
            float4 l2g = *(const float4*)(ln2g + l*128 + lane*4);
            float4 l2b = *(const float4*)(ln2b + l*128 + lane*4);
            float g2bs = g2b[l];
            for (int q = 0; q < 8; q++) {
                int r = wid * 8 + q;
                float4* u4 = (float4*)(sU + r*128);
                float4 x = u4[lane];
                float s  = x.x + x.y + x.z + x.w;
                float ss = x.x*x.x + x.y*x.y + x.z*x.z + x.w*x.w;
                #pragma unroll
                for (int o = 16; o; o >>= 1) {
                    s  += __shfl_xor_sync(0xffffffffu, s,  o);
                    ss += __shfl_xor_sync(0xffffffffu, ss, o);
                }
                float m   = s * (1.f/128.f);
                float var = ss * (1.f/128.f) - m*m;
                float accg = 0.f;
                {
                    float t0 = m*w1v.x + b1v.x; accg += (t0/(1.f+expf(-t0)))*w2v.x;
                    float t1 = m*w1v.y + b1v.y; accg += (t1/(1.f+expf(-t1)))*w2v.y;
                    float t2 = m*w1v.z + b1v.z; accg += (t2/(1.f+expf(-t2)))*w2v.z;
                    float t3 = m*w1v.w + b1v.w; accg += (t3/(1.f+expf(-t3)))*w2v.w;
                }
                #pragma unroll
                for (int o = 16; o; o >>= 1) accg += __shfl_xor_sync(0xffffffffu, accg, o);
                float gate = 1.f / (1.f + expf(-(accg + g2bs)));
                float4 vg; vg.x = x.x*gate; vg.y = x.y*gate; vg.z = x.z*gate; vg.w = x.w*gate;
                u4[lane] = vg;
                float mu2 = m * gate;
                float rsg = rsqrtf(var * gate * gate + 1e-5f);
                float4 hn;
                hn.x = (vg.x - mu2)*rsg*l2g.x + l2b.x;
                hn.y = (vg.y - mu2)*rsg*l2g.y + l2b.y;
                hn.z = (vg.z - mu2)*rsg*l2g.z + l2b.z;
                hn.w = (vg.w - mu2)*rsg*l2g.w + l2b.w;
                ((float4*)(W1 + r*128))[lane] = hn;
            }
        }
        __syncthreads();

        // ---- horizontal pack LN2 -> P ----
        for (int idx = tid; idx < 4096; idx += 256) {
            int r = idx >> 6, p = idx & 63;
            uint32_t h, lo;
            split_pair(W1[r*128 + 2*p], W1[r*128 + 2*p + 1], h, lo);
            Ph[r*PST + p] = h; Pl[r*PST + p] = lo;
        }

        // ---- MLP: chunked K accumulation ----
        {
            float accZ[2][4][4]; ZERO_ACC(accZ);
            uint32_t* Qh = XQu;            // reuse sXq region (stride PST)
            uint32_t* Ql = XVu;
            for (int ch = 0; ch < 4; ch++) {
                float accM[2][4][4]; ZERO_ACC(accM);
                gemm_stream(Ph, Pl,
                            g_WH + WOFF_M1(l) + ch*128, g_WL + WOFF_M1(l) + ch*128,
                            512, 8, wst, accM, tid, lane, wm, wn);
                // silu(acc + bm1) -> pack into Q
                #pragma unroll
                for (int mi = 0; mi < 2; mi++)
                    #pragma unroll
                    for (int ni = 0; ni < 4; ni++)
                        #pragma unroll
                        for (int hf = 0; hf < 2; hf++) {
                            int r = wm + mi*16 + hf*8 + (lane >> 2);
                            int c = wn + ni*8 + 2*(lane & 3);
                            float v0 = accM[mi][ni][hf*2+0] + bm1[l*512 + ch*128 + c];
                            float v1 = accM[mi][ni][hf*2+1] + bm1[l*512 + ch*128 + c + 1];
                            v0 = v0 / (1.f + expf(-v0));
                            v1 = v1 / (1.f + expf(-v1));
                            uint32_t h, lo;
                            split_pair(v0, v1, h, lo);
                            Qh[r*PST + (c >> 1)] = h;
                            Ql[r*PST + (c >> 1)] = lo;
                        }
                gemm_stream(Qh, Ql,
                            g_WH + WOFF_M2(l) + (size_t)(ch*64)*128,
                            g_WL + WOFF_M2(l) + (size_t)(ch*64)*128,
                            128, 8, wst, accZ, tid, lane, wm, wn);
            }
            __syncthreads();
            #pragma unroll
            for (int mi = 0; mi < 2; mi++)
                #pragma unroll
                for (int ni = 0; ni < 4; ni++)
                    #pragma unroll
                    for (int hf = 0; hf < 2; hf++) {
                        int r = wm + mi*16 + hf*8 + (lane >> 2);
                        int c = wn + ni*8 + 2*(lane & 3);
                        sZ[r*128 + c]     = accZ[mi][ni][hf*2+0] + bm2[l*128 + c]     + sU[r*128 + c];
                        sZ[r*128 + c + 1] = accZ[mi][ni][hf*2+1] + bm2[l*128 + c + 1] + sU[r*128 + c + 1];
                    }
        }
        __syncthreads();
    }

    // ---- outputs ----
    {
        float4* zo = (float4*)(Zdst + (size_t)bt * NN * DD);
        const float4* zs = (const float4*)sZ;
        for (int idx = tid; idx < 2048; idx += 256) zo[idx] = zs[idx];
        if (Sdst) {
            int d = tid & 127, hf = tid >> 7;
            float ps = 0.f;
            for (int i = hf*32; i < hf*32 + 32; i++) ps += sZ[i*128 + d];
            sexp[hf*128 + d] = ps;
            __syncthreads();
            if (tid < 128)
                Sdst[(size_t)bt*128 + tid] = (sexp[tid] + sexp[128 + tid]) * (1.f/64.f);
        }
    }
}

// ---------------- setup kernels ----------------
__global__ void pack_w_kernel(
    const float* __restrict__ Wp, const float* __restrict__ Wlin,
    const float* __restrict__ Wval, const float* __restrict__ Wout,
    const float* __restrict__ Wm1, const float* __restrict__ Wm2)
{
    int idx = blockIdx.x * blockDim.x + threadIdx.x;
    if (idx >= WTOT) return;
    const float* W; int N, off;
    if (idx < 8192) { W = Wp; N = DD; off = idx; }
    else {
        int j = idx - 8192, l = j / WSEG, u = j % WSEG;
        if (u < 8192)       { W = Wlin + (size_t)l*DD*DD; N = DD; off = u; }
        else if (u < 16384) { W = Wval + (size_t)l*DD*DD; N = DD; off = u - 8192; }
        else if (u < 24576) { W = Wout + (size_t)l*DD*DD; N = DD; off = u - 16384; }
        else if (u < 57344) { W = Wm1  + (size_t)l*DD*D4; N = D4; off = u - 24576; }
        else                { W = Wm2  + (size_t)l*D4*DD; N = DD; off = u - 57344; }
    }
    int k2 = off / N, n = off - k2 * N;
    uint32_t h, l2;
    split_pair(W[(size_t)(2*k2) * N + n], W[(size_t)(2*k2+1) * N + n], h, l2);
    g_WH[idx] = h; g_WL[idx] = l2;
}

__global__ void adj_kernel(const float* __restrict__ A0, const float* __restrict__ P,
                           const float* __restrict__ Qm, const float* __restrict__ alphap,
                           float* __restrict__ A)
{
    int i = blockIdx.x, j = threadIdx.x;
    float a0 = A0[i*NN + j];
    float dot = 0.f;
    #pragma unroll
    for (int r = 0; r < 8; r++) dot += P[i*8 + r] * Qm[j*8 + r];
    float sp = (dot > 20.f) ? dot : log1pf(expf(dot));
    float ad = (a0 > 0.f) ? sp : 0.f;
    float a  = a0 * (1.f + alphap[0] * ad);
    __shared__ float sbuf[NN];
    sbuf[j] = a;
    __syncthreads();
    for (int st = 32; st >= 1; st >>= 1) {
        if (j < st) sbuf[j] += sbuf[j + st];
        __syncthreads();
    }
    A[i*NN + j] = a / (sbuf[0] + 1e-8f);
}

__global__ void pack_adj_kernel(const float* __restrict__ A)
{
    int idx = blockIdx.x * blockDim.x + threadIdx.x;
    if (idx >= NN*32) return;
    int i = idx >> 5, j2 = idx & 31;
    uint32_t h, l;
    split_pair(A[i*NN + 2*j2], A[i*NN + 2*j2 + 1], h, l);
    g_AJH[idx] = h; g_AJL[idx] = l;
}

__global__ void rowptr_kernel(const int* __restrict__ src, int E)
{
    int t = threadIdx.x;
    if (t > NN) return;
    int lo = 0, hi = E;
    while (lo < hi) { int mid = (lo + hi) >> 1; if (src[mid] < t) lo = mid + 1; else hi = mid; }
    g_rowptr[t] = lo;
}

__global__ void edge_kernel(const int* __restrict__ src, const int* __restrict__ dst,
                            const float* __restrict__ A0, int E)
{
    int e = blockIdx.x * blockDim.x + threadIdx.x;
    if (e < E) g_logA0[e] = logf(A0[src[e]*NN + dst[e]] + 1e-8f);
}

__global__ void copy_kernel(const float* __restrict__ src, float* __restrict__ dst, int n4)
{
    int i = blockIdx.x * blockDim.x + threadIdx.x;
    if (i < n4) ((float4*)dst)[i] = ((const float4*)src)[i];
}

__global__ void fill0_kernel(float* __restrict__ p, int n)
{
    int i = blockIdx.x * blockDim.x + threadIdx.x;
    if (i < n) p[i] = 0.f;
}

// ---------------- host driver ----------------
extern "C" void kernel_launch(void* const* d_in, const int* in_sizes, int n_in,
                              void* d_out, int out_size)
{
    const float* X     = (const float*)d_in[0];
    const float* Wp    = (const float*)d_in[1];
    const float* bp    = (const float*)d_in[2];
    const float* P     = (const float*)d_in[3];
    const float* Qm    = (const float*)d_in[4];
    const float* alpha = (const float*)d_in[5];
    const float* ln1g  = (const float*)d_in[6];
    const float* ln1b  = (const float*)d_in[7];
    const float* Wlin  = (const float*)d_in[8];
    const float* Wval  = (const float*)d_in[9];
    const float* a_att = (const float*)d_in[10];
    const float* Wout  = (const float*)d_in[11];
    const float* g1w   = (const float*)d_in[12];
    const float* g1b   = (const float*)d_in[13];
    const float* g2w   = (const float*)d_in[14];
    const float* g2b   = (const float*)d_in[15];
    const float* ln2g  = (const float*)d_in[16];
    const float* ln2b  = (const float*)d_in[17];
    const float* Wm1   = (const float*)d_in[18];
    const float* bm1   = (const float*)d_in[19];
    const float* Wm2   = (const float*)d_in[20];
    const float* bm2   = (const float*)d_in[21];
    const float* A0    = (const float*)d_in[22];
    const int*   srcI  = (const int*)d_in[24];
    const int*   dstI  = (const int*)d_in[25];
    int E = in_sizes[24];
    float* out = (float*)d_out;

    float *Z, *A;
    cudaGetSymbolAddress((void**)&Z, g_Z);
    cudaGetSymbolAddress((void**)&A, g_A);

    cudaFuncSetAttribute(fused_kernel, cudaFuncAttributeMaxDynamicSharedMemorySize,
                         SM_TOT * 4);

    const int ZN = NROWS * DD;
    const int SN = NBT * DD;
    const int AN = NN * NN;
    float* Zdst = (out_size >= ZN) ? out : Z;
    float* Sdst = (out_size >= ZN + SN) ? (out + ZN) : nullptr;

    pack_w_kernel<<<(WTOT + 255) / 256, 256>>>(Wp, Wlin, Wval, Wout, Wm1, Wm2);
    adj_kernel<<<NN, NN>>>(A0, P, Qm, alpha, A);
    pack_adj_kernel<<<(NN*32 + 255) / 256, 256>>>(A);
    rowptr_kernel<<<1, 128>>>(srcI, E);
    edge_kernel<<<(E + 127) / 128, 128>>>(srcI, dstI, A0, E);

    fused_kernel<<<NBT, 256, SM_TOT * 4>>>(
        X, bp, ln1g, ln1b, a_att, g1w, g1b, g2w, g2b,
        ln2g, ln2b, bm1, bm2, dstI, Zdst, Sdst);

    if (out_size >= ZN + SN + AN)
        copy_kernel<<<(AN / 4 + 255) / 256, 256>>>(A, out + ZN + SN, AN / 4);
    int tail = out_size - (ZN + SN + AN);
    if (tail > 0)
        fill0_kernel<<<(tail + 255) / 256, 256>>>(out + ZN + SN + AN, tail);
}

// round 14
// speedup vs baseline: 1.1871x; 1.0037x over previous
#include <cuda_runtime.h>
#include <math.h>
#include <stdint.h>

// ---------------- problem constants ----------------
#define NBT 512
#define NN 64
#define DD 128
#define HH 4
#define DHH 32
#define LL 3
#define D4 512
#define NROWS (NBT*NN)
#define MAXE 4096

// packed weights (u32 units; [K/2][N] k2-major), raw values (LN applied in-kernel)
#define WOFF_WP   0
#define WSEG      90112
#define WOFF_LIN(l)  (8192 + (l)*WSEG)
#define WOFF_VAL(l)  (8192 + (l)*WSEG + 8192)
#define WOFF_OUT(l)  (8192 + (l)*WSEG + 16384)
#define WOFF_M1(l)   (8192 + (l)*WSEG + 24576)
#define WOFF_M2(l)   (8192 + (l)*WSEG + 57344)
#define WTOT      (8192 + LL*WSEG)

// ---------------- device globals ----------------
__device__ float g_Z[NROWS*DD];          // fallback Z output
__device__ float g_A[NN*NN];
__device__ float g_logA0[MAXE];
__device__ int   g_rowptr[NN+1];
__device__ uint32_t g_WH[WTOT], g_WL[WTOT];
__device__ uint32_t g_AJH[NN*32], g_AJL[NN*32];   // adjacency packed pairs along j

// ---------------- helpers ----------------
__device__ __forceinline__ uint32_t smem_u32(const void* p) {
    uint32_t a;
    asm("{ .reg .u64 t; cvta.to.shared.u64 t, %1; cvt.u32.u64 %0, t; }" : "=r"(a) : "l"(p));
    return a;
}
__device__ __forceinline__ void cp_async16(void* smem, const void* gmem) {
    unsigned sa = smem_u32(smem);
    asm volatile("cp.async.cg.shared.global [%0], [%1], 16;\n" :: "r"(sa), "l"(gmem));
}
__device__ __forceinline__ uint32_t pack_bf16x2(float x0, float x1) {
    uint32_t r;
    asm("cvt.rn.bf16x2.f32 %0, %1, %2;" : "=r"(r) : "f"(x1), "f"(x0));
    return r;
}
__device__ __forceinline__ void split_pair(float x0, float x1, uint32_t& h2, uint32_t& l2) {
    h2 = pack_bf16x2(x0, x1);
    float h0 = __uint_as_float(h2 << 16);
    float h1 = __uint_as_float(h2 & 0xffff0000u);
    l2 = pack_bf16x2(x0 - h0, x1 - h1);
}
__device__ __forceinline__ void mma_bf16(float* c, const uint32_t* a, const uint32_t* b) {
    asm volatile("mma.sync.aligned.m16n8k16.row.col.f32.bf16.bf16.f32 "
        "{%0,%1,%2,%3}, {%4,%5,%6,%7}, {%8,%9}, {%0,%1,%2,%3};"
        : "+f"(c[0]), "+f"(c[1]), "+f"(c[2]), "+f"(c[3])
        : "r"(a[0]), "r"(a[1]), "r"(a[2]), "r"(a[3]), "r"(b[0]), "r"(b[1]));
}

// ---------------- smem layout (4B units) ----------------
#define SM_Z    0
#define SM_U    8192
#define SM_W1   16384
#define SM_XQ   24576      // 64*129
#define SM_XV   32832      // 64*129
#define SM_PH   41088      // 64*68 u32
#define SM_PL   45440
#define SM_WST  49792      // 3*2176 u32
#define SM_EXP  56320      // 8*64
#define SM_DSTW 56832      // 8*64 int
#define SM_SA   57344      // 128
#define SM_TOT  57472      // *4 = 229,888 B
#define XST 129
#define PST 68

// ---------------- block-level gemm: M=64, N=128, A resident, B streamed ------
__device__ __forceinline__ void gemm_stream(
    const uint32_t* __restrict__ Ah, const uint32_t* __restrict__ Al,
    const uint32_t* __restrict__ Bh, const uint32_t* __restrict__ Bl,
    int bst, int ktiles, uint32_t* wst,
    float (&acc)[2][4][4], int tid, int lane, int wm, int wn)
{
    const int bk2 = tid >> 5, bc4 = (tid & 31) * 4;
    __syncthreads();   // prior phase writes visible; wst free
#define GISSUE(t) { \
        uint32_t* S_ = wst + ((t) % 3) * 2176; \
        cp_async16(S_ + bk2*136 + bc4,        Bh + (size_t)((t)*8 + bk2)*bst + bc4); \
        cp_async16(S_ + 1088 + bk2*136 + bc4, Bl + (size_t)((t)*8 + bk2)*bst + bc4); \
        asm volatile("cp.async.commit_group;\n"); }
    GISSUE(0); GISSUE(1);
    for (int t = 0; t < ktiles; t++) {
        if (t < ktiles - 1) asm volatile("cp.async.wait_group 1;\n");
        else                asm volatile("cp.async.wait_group 0;\n");
        __syncthreads();
        if (t + 2 < ktiles) GISSUE(t + 2);
        const uint32_t* Sh = wst + (t % 3) * 2176;
        const uint32_t* Sl = Sh + 1088;
        const int r0 = wm + (lane >> 2);
        const int ka = t * 8 + (lane & 3);
        const int kb_ = lane & 3;
        uint32_t ah[2][4], al2[2][4], bh[4][2], bl[4][2];
        #pragma unroll
        for (int mi = 0; mi < 2; mi++) {
            const int rb = (r0 + mi * 16) * PST;
            ah[mi][0]  = Ah[rb + ka];
            ah[mi][1]  = Ah[rb + 8 * PST + ka];
            ah[mi][2]  = Ah[rb + ka + 4];
            ah[mi][3]  = Ah[rb + 8 * PST + ka + 4];
            al2[mi][0] = Al[rb + ka];
            al2[mi][1] = Al[rb + 8 * PST + ka];
            al2[mi][2] = Al[rb + ka + 4];
            al2[mi][3] = Al[rb + 8 * PST + ka + 4];
        }
        const int bn0 = wn + (lane >> 2);
        #pragma unroll
        for (int ni = 0; ni < 4; ni++) {
            bh[ni][0] = Sh[kb_*136 + bn0 + ni*8];
            bh[ni][1] = Sh[(kb_+4)*136 + bn0 + ni*8];
            bl[ni][0] = Sl[kb_*136 + bn0 + ni*8];
            bl[ni][1] = Sl[(kb_+4)*136 + bn0 + ni*8];
        }
        #pragma unroll
        for (int mi = 0; mi < 2; mi++)
            #pragma unroll
            for (int ni = 0; ni < 4; ni++) {
                mma_bf16(acc[mi][ni], al2[mi], bh[ni]);
                mma_bf16(acc[mi][ni], ah[mi],  bl[ni]);
                mma_bf16(acc[mi][ni], ah[mi],  bh[ni]);
            }
    }
#undef GISSUE
}

// ---------------- block gemm with BOTH operands resident (hmix) --------------
__device__ __forceinline__ void gemm_resident(
    const uint32_t* __restrict__ Ah, const uint32_t* __restrict__ Al,
    const uint32_t* __restrict__ BhR, const uint32_t* __restrict__ BlR,
    int ktiles, float (&acc)[2][4][4], int lane, int wm, int wn)
{
    for (int t = 0; t < ktiles; t++) {
        const int r0 = wm + (lane >> 2);
        const int ka = t * 8 + (lane & 3);
        uint32_t ah[2][4], al2[2][4], bh[4][2], bl[4][2];
        #pragma unroll
        for (int mi = 0; mi < 2; mi++) {
            const int rb = (r0 + mi * 16) * PST;
            ah[mi][0]  = Ah[rb + ka];
            ah[mi][1]  = Ah[rb + 8 * PST + ka];
            ah[mi][2]  = Ah[rb + ka + 4];
            ah[mi][3]  = Ah[rb + 8 * PST + ka + 4];
            al2[mi][0] = Al[rb + ka];
            al2[mi][1] = Al[rb + 8 * PST + ka];
            al2[mi][2] = Al[rb + ka + 4];
            al2[mi][3] = Al[rb + 8 * PST + ka + 4];
        }
        const int bn0 = wn + (lane >> 2);
        #pragma unroll
        for (int ni = 0; ni < 4; ni++) {
            bh[ni][0] = BhR[ka*136 + bn0 + ni*8];
            bh[ni][1] = BhR[(ka+4)*136 + bn0 + ni*8];
            bl[ni][0] = BlR[ka*136 + bn0 + ni*8];
            bl[ni][1] = BlR[(ka+4)*136 + bn0 + ni*8];
        }
        #pragma unroll
        for (int mi = 0; mi < 2; mi++)
            #pragma unroll
            for (int ni = 0; ni < 4; ni++) {
                mma_bf16(acc[mi][ni], al2[mi], bh[ni]);
                mma_bf16(acc[mi][ni], ah[mi],  bl[ni]);
                mma_bf16(acc[mi][ni], ah[mi],  bh[ni]);
            }
    }
}

#define ZERO_ACC(a) { _Pragma("unroll") for (int mi_=0;mi_<2;mi_++) \
    _Pragma("unroll") for (int ni_=0;ni_<4;ni_++) \
    _Pragma("unroll") for (int q_=0;q_<4;q_++) (a)[mi_][ni_][q_] = 0.f; }

// ---------------- the fused per-bt kernel ----------------
extern __shared__ float smf[];
__global__ __launch_bounds__(256) void fused_kernel(
    const float* __restrict__ X, const float* __restrict__ bp,
    const float* __restrict__ ln1g, const float* __restrict__ ln1b,
    const float* __restrict__ a_att,
    const float* __restrict__ g1w, const float* __restrict__ g1b,
    const float* __restrict__ g2w, const float* __restrict__ g2b,
    const float* __restrict__ ln2g, const float* __restrict__ ln2b,
    const float* __restrict__ bm1, const float* __restrict__ bm2,
    const int* __restrict__ dstI,
    float* __restrict__ Zdst, float* __restrict__ Sdst)
{
    const int bt   = blockIdx.x;
    const int tid  = threadIdx.x;
    const int lane = tid & 31;
    const int wid  = tid >> 5;
    const int wm   = (wid & 1) * 32;
    const int wn   = (wid >> 1) * 32;

    float*    sZ  = smf + SM_Z;
    float*    sU  = smf + SM_U;
    float*    W1  = smf + SM_W1;
    float*    sXq = smf + SM_XQ;
    float*    sXv = smf + SM_XV;
    uint32_t* XQu = (uint32_t*)sXq;
    uint32_t* XVu = (uint32_t*)sXv;
    uint32_t* Ph  = (uint32_t*)(smf + SM_PH);
    uint32_t* Pl  = (uint32_t*)(smf + SM_PL);
    uint32_t* wst = (uint32_t*)(smf + SM_WST);
    float*    sexp  = smf + SM_EXP;
    int*      sdstW = (int*)(smf + SM_DSTW);
    float*    sa    = smf + SM_SA;

    // ---- input pack: X slab -> P ----
    {
        const float* Xb = X + (size_t)bt * NN * DD;
        for (int idx = tid; idx < 4096; idx += 256) {
            int r = idx >> 6, p = idx & 63;
            float2 x = *(const float2*)(Xb + r * 128 + 2 * p);
            uint32_t h, l;
            split_pair(x.x, x.y, h, l);
            Ph[r * PST + p] = h; Pl[r * PST + p] = l;
        }
    }
    // proj: sZ = X@Wp + bp
    {
        float acc[2][4][4]; ZERO_ACC(acc);
        gemm_stream(Ph, Pl, g_WH + WOFF_WP, g_WL + WOFF_WP, 128, 8, wst,
                    acc, tid, lane, wm, wn);
        #pragma unroll
        for (int mi = 0; mi < 2; mi++)
            #pragma unroll
            for (int ni = 0; ni < 4; ni++)
                #pragma unroll
                for (int hf = 0; hf < 2; hf++) {
                    int r = wm + mi*16 + hf*8 + (lane >> 2);
                    int c = wn + ni*8 + 2*(lane & 3);
                    sZ[r*128 + c]     = acc[mi][ni][hf*2+0] + bp[c];
                    sZ[r*128 + c + 1] = acc[mi][ni][hf*2+1] + bp[c+1];
                }
    }
    __syncthreads();

    for (int l = 0; l < LL; l++) {
        // ---- LN1 -> W1 ----
        {
            float ga[4], ba[4];
            #pragma unroll
            for (int q = 0; q < 4; q++) {
                ga[q] = ln1g[l*128 + lane + 32*q];
                ba[q] = ln1b[l*128 + lane + 32*q];
            }
            for (int q = 0; q < 8; q++) {
                int r = wid * 8 + q;
                const float* zr = sZ + r * 128;
                float v0 = zr[lane], v1 = zr[lane+32], v2 = zr[lane+64], v3 = zr[lane+96];
                float s = v0+v1+v2+v3, ss = v0*v0+v1*v1+v2*v2+v3*v3;
                #pragma unroll
                for (int o = 16; o; o >>= 1) {
                    s  += __shfl_xor_sync(0xffffffffu, s,  o);
                    ss += __shfl_xor_sync(0xffffffffu, ss, o);
                }
                float mu = s * (1.f/128.f);
                float rs = rsqrtf(ss * (1.f/128.f) - mu*mu + 1e-5f);
                float* hr = W1 + r * 128;
                hr[lane]    = (v0-mu)*rs*ga[0] + ba[0];
                hr[lane+32] = (v1-mu)*rs*ga[1] + ba[1];
                hr[lane+64] = (v2-mu)*rs*ga[2] + ba[2];
                hr[lane+96] = (v3-mu)*rs*ga[3] + ba[3];
            }
            if (tid < 128) sa[tid] = a_att[l*128 + tid];
        }
        __syncthreads();

        // ---- vertical pack Hn -> XQu/XVu; adjacency -> P ----
        for (int idx = tid; idx < 4096; idx += 256) {
            int j2 = idx >> 7, d = idx & 127;
            uint32_t h, lo;
            split_pair(W1[(2*j2)*128 + d], W1[(2*j2+1)*128 + d], h, lo);
            XQu[j2*136 + d] = h; XVu[j2*136 + d] = lo;
        }
        for (int idx = tid; idx < 2048; idx += 256) {
            int i = idx >> 5, j2 = idx & 31;
            Ph[i*PST + j2] = g_AJH[i*32 + j2];
            Pl[i*PST + j2] = g_AJL[i*32 + j2];
        }
        __syncthreads();

        // ---- hmix: sU = sZ + A@Hn ----
        {
            float acc[2][4][4]; ZERO_ACC(acc);
            gemm_resident(Ph, Pl, XQu, XVu, 4, acc, lane, wm, wn);
            #pragma unroll
            for (int mi = 0; mi < 2; mi++)
                #pragma unroll
                for (int ni = 0; ni < 4; ni++)
                    #pragma unroll
                    for (int hf = 0; hf < 2; hf++) {
                        int r = wm + mi*16 + hf*8 + (lane >> 2);
                        int c = wn + ni*8 + 2*(lane & 3);
                        sU[r*128 + c]     = sZ[r*128 + c]     + acc[mi][ni][hf*2+0];
                        sU[r*128 + c + 1] = sZ[r*128 + c + 1] + acc[mi][ni][hf*2+1];
                    }
        }
        __syncthreads();

        // ---- horizontal pack Hn -> P ----
        for (int idx = tid; idx < 4096; idx += 256) {
            int r = idx >> 6, p = idx & 63;
            uint32_t h, lo;
            split_pair(W1[r*128 + 2*p], W1[r*128 + 2*p + 1], h, lo);
            Ph[r*PST + p] = h; Pl[r*PST + p] = lo;
        }

        // ---- Xq / Xv gemms ----
        for (int qv = 0; qv < 2; qv++) {
            float acc[2][4][4]; ZERO_ACC(acc);
            int off = qv ? WOFF_VAL(l) : WOFF_LIN(l);
            gemm_stream(Ph, Pl, g_WH + off, g_WL + off, 128, 8, wst,
                        acc, tid, lane, wm, wn);
            float* dst = qv ? sXv : sXq;
            #pragma unroll
            for (int mi = 0; mi < 2; mi++)
                #pragma unroll
                for (int ni = 0; ni < 4; ni++)
                    #pragma unroll
                    for (int hf = 0; hf < 2; hf++) {
                        int r = wm + mi*16 + hf*8 + (lane >> 2);
                        int c = wn + ni*8 + 2*(lane & 3);
                        dst[r*XST + c]     = acc[mi][ni][hf*2+0];
                        dst[r*XST + c + 1] = acc[mi][ni][hf*2+1];
                    }
        }
        __syncthreads();

        // ---- attention: warp = (head h, parity); Y packed -> P ----
        {
            const int h    = wid & 3;
            const int half = wid >> 2;
            const float a  = sa[h*32 + lane];
            float* myexp = sexp + wid * 64;
            int*   mydst = sdstW + wid * 64;
            for (int i = half; i < NN; i += 2) {
                const int e0  = g_rowptr[i];
                const int deg = g_rowptr[i+1] - e0;
                const float* qrow = sXq + i*XST + h*32;
                float vmax = -1e30f;
                for (int kb = 0; kb < deg; kb += 32) {
                    const int k = kb + lane;
                    const bool ok = (k < deg);
                    const int j = ok ? dstI[e0 + k] : 0;
                    const float* jrow = sXq + j*XST + h*32;
                    float accd = 0.f;
                    #pragma unroll
                    for (int d = 0; d < 32; d++) {
                        float x = qrow[d] + jrow[d];
                        x = (x > 0.f) ? x : 0.2f * x;
                        accd = fmaf(x, sa[h*32 + d], accd);
                    }
                    float v = ok ? (accd + g_logA0[e0 + k]) : -1e30f;
                    if (ok) { myexp[k] = v; mydst[k] = j; }
                    vmax = fmaxf(vmax, v);
                }
                #pragma unroll
                for (int o = 16; o; o >>= 1)
                    vmax = fmaxf(vmax, __shfl_xor_sync(0xffffffffu, vmax, o));
                __syncwarp();
                float den = 0.f;
                for (int kb = 0; kb < deg; kb += 32) {
                    const int k = kb + lane;
                    if (k < deg) {
                        float ev = expf(myexp[k] - vmax);
                        myexp[k] = ev;
                        den += ev;
                    }
                }
                #pragma unroll
                for (int o = 16; o; o >>= 1) den += __shfl_xor_sync(0xffffffffu, den, o);
                __syncwarp();
                const float inv = 1.f / den;
                float y = 0.f;
                #pragma unroll 4
                for (int k = 0; k < deg; k++)
                    y = fmaf(myexp[k], sXv[mydst[k]*XST + h*32 + lane], y);
                float yf = y * inv;
                float yp = __shfl_down_sync(0xffffffffu, yf, 1);
                if (!(lane & 1)) {
                    uint32_t hh, ll;
                    split_pair(yf, yp, hh, ll);
                    Ph[i*PST + h*16 + (lane >> 1)] = hh;
                    Pl[i*PST + h*16 + (lane >> 1)] = ll;
                }
                __syncwarp();
            }
            (void)a;
        }

        // ---- Wout gemm: sU += Y@Wout ----
        {
            float acc[2][4][4]; ZERO_ACC(acc);
            gemm_stream(Ph, Pl, g_WH + WOFF_OUT(l), g_WL + WOFF_OUT(l), 128, 8, wst,
                        acc, tid, lane, wm, wn);
            #pragma unroll
            for (int mi = 0; mi < 2; mi++)
                #pragma unroll
                for (int ni = 0; ni < 4; ni++)
                    #pragma unroll
                    for (int hf = 0; hf < 2; hf++) {
                        int r = wm + mi*16 + hf*8 + (lane >> 2);
                        int c = wn + ni*8 + 2*(lane & 3);
                        sU[r*128 + c]     += acc[mi][ni][hf*2+0];
                        sU[r*128 + c + 1] += acc[mi][ni][hf*2+1];
                    }
        }
        __syncthreads();

        // ---- gate + LN2 -> sU gated (in place), W1 = LN2(sU) ----
        {
            float4 w1v = *(const float4*)(g1w + l*128 + lane*4);
            float4 b1v = *(const float4*)(g1b + l*128 + lane*4);
            float4 w2v = *(const float4*)(g2w + l*128 + lane*4);
            float4 l2g = *(const float4*)(ln2g + l*128 + lane*4);
            float4 l2b = *(const float4*)(ln2b + l*128 + lane*4);
            float g2bs = g2b[l];
            for (int q = 0; q < 8; q++) {
                int r = wid * 8 + q;
                float4* u4 = (float4*)(sU + r*128);
                float4 x = u4[lane];
                float s  = x.x + x.y + x.z + x.w;
                float ss = x.x*x.x + x.y*x.y + x.z*x.z + x.w*x.w;
                #pragma unroll
                for (int o = 16; o; o >>= 1) {
                    s  += __shfl_xor_sync(0xffffffffu, s,  o);
                    ss += __shfl_xor_sync(0xffffffffu, ss, o);
                }
                float m   = s * (1.f/128.f);
                float var = ss * (1.f/128.f) - m*m;
                float accg = 0.f;
                {
                    float t0 = m*w1v.x + b1v.x; accg += (t0/(1.f+expf(-t0)))*w2v.x;
                    float t1 = m*w1v.y + b1v.y; accg += (t1/(1.f+expf(-t1)))*w2v.y;
                    float t2 = m*w1v.z + b1v.z; accg += (t2/(1.f+expf(-t2)))*w2v.z;
                    float t3 = m*w1v.w + b1v.w; accg += (t3/(1.f+expf(-t3)))*w2v.w;
                }
                #pragma unroll
                for (int o = 16; o; o >>= 1) accg += __shfl_xor_sync(0xffffffffu, accg, o);
                float gate = 1.f / (1.f + expf(-(accg + g2bs)));
                float4 vg; vg.x = x.x*gate; vg.y = x.y*gate; vg.z = x.z*gate; vg.w = x.w*gate;
                u4[lane] = vg;
                float mu2 = m * gate;
                float rsg = rsqrtf(var * gate * gate + 1e-5f);
                float4 hn;
                hn.x = (vg.x - mu2)*rsg*l2g.x + l2b.x;
                hn.y = (vg.y - mu2)*rsg*l2g.y + l2b.y;
                hn.z = (vg.z - mu2)*rsg*l2g.z + l2b.z;
                hn.w = (vg.w - mu2)*rsg*l2g.w + l2b.w;
                ((float4*)(W1 + r*128))[lane] = hn;
            }
        }
        __syncthreads();

        // ---- horizontal pack LN2 -> P ----
        for (int idx = tid; idx < 4096; idx += 256) {
            int r = idx >> 6, p = idx & 63;
            uint32_t h, lo;
            split_pair(W1[r*128 + 2*p], W1[r*128 + 2*p + 1], h, lo);
            Ph[r*PST + p] = h; Pl[r*PST + p] = lo;
        }

        // ---- MLP: chunked K accumulation ----
        {
            float accZ[2][4][4]; ZERO_ACC(accZ);
            uint32_t* Qh = XQu;            // reuse sXq region (stride PST)
            uint32_t* Ql = XVu;
            for (int ch = 0; ch < 4; ch++) {
                float accM[2][4][4]; ZERO_ACC(accM);
                gemm_stream(Ph, Pl,
                            g_WH + WOFF_M1(l) + ch*128, g_WL + WOFF_M1(l) + ch*128,
                            512, 8, wst, accM, tid, lane, wm, wn);
                // silu(acc + bm1) -> pack into Q
                #pragma unroll
                for (int mi = 0; mi < 2; mi++)
                    #pragma unroll
                    for (int ni = 0; ni < 4; ni++)
                        #pragma unroll
                        for (int hf = 0; hf < 2; hf++) {
                            int r = wm + mi*16 + hf*8 + (lane >> 2);
                            int c = wn + ni*8 + 2*(lane & 3);
                            float v0 = accM[mi][ni][hf*2+0] + bm1[l*512 + ch*128 + c];
                            float v1 = accM[mi][ni][hf*2+1] + bm1[l*512 + ch*128 + c + 1];
                            v0 = v0 / (1.f + expf(-v0));
                            v1 = v1 / (1.f + expf(-v1));
                            uint32_t h, lo;
                            split_pair(v0, v1, h, lo);
                            Qh[r*PST + (c >> 1)] = h;
                            Ql[r*PST + (c >> 1)] = lo;
                        }
                gemm_stream(Qh, Ql,
                            g_WH + WOFF_M2(l) + (size_t)(ch*64)*128,
                            g_WL + WOFF_M2(l) + (size_t)(ch*64)*128,
                            128, 8, wst, accZ, tid, lane, wm, wn);
            }
            __syncthreads();
            #pragma unroll
            for (int mi = 0; mi < 2; mi++)
                #pragma unroll
                for (int ni = 0; ni < 4; ni++)
                    #pragma unroll
                    for (int hf = 0; hf < 2; hf++) {
                        int r = wm + mi*16 + hf*8 + (lane >> 2);
                        int c = wn + ni*8 + 2*(lane & 3);
                        sZ[r*128 + c]     = accZ[mi][ni][hf*2+0] + bm2[l*128 + c]     + sU[r*128 + c];
                        sZ[r*128 + c + 1] = accZ[mi][ni][hf*2+1] + bm2[l*128 + c + 1] + sU[r*128 + c + 1];
                    }
        }
        __syncthreads();
    }

    // ---- outputs ----
    {
        float4* zo = (float4*)(Zdst + (size_t)bt * NN * DD);
        const float4* zs = (const float4*)sZ;
        for (int idx = tid; idx < 2048; idx += 256) zo[idx] = zs[idx];
        if (Sdst) {
            int d = tid & 127, hf = tid >> 7;
            float ps = 0.f;
            for (int i = hf*32; i < hf*32 + 32; i++) ps += sZ[i*128 + d];
            sexp[hf*128 + d] = ps;
            __syncthreads();
            if (tid < 128)
                Sdst[(size_t)bt*128 + tid] = (sexp[tid] + sexp[128 + tid]) * (1.f/64.f);
        }
    }
}

// ---------------- setup kernels ----------------
__global__ void pack_w_kernel(
    const float* __restrict__ Wp, const float* __restrict__ Wlin,
    const float* __restrict__ Wval, const float* __restrict__ Wout,
    const float* __restrict__ Wm1, const float* __restrict__ Wm2)
{
    int idx = blockIdx.x * blockDim.x + threadIdx.x;
    if (idx >= WTOT) return;
    const float* W; int N, off;
    if (idx < 8192) { W = Wp; N = DD; off = idx; }
    else {
        int j = idx - 8192, l = j / WSEG, u = j % WSEG;
        if (u < 8192)       { W = Wlin + (size_t)l*DD*DD; N = DD; off = u; }
        else if (u < 16384) { W = Wval + (size_t)l*DD*DD; N = DD; off = u - 8192; }
        else if (u < 24576) { W = Wout + (size_t)l*DD*DD; N = DD; off = u - 16384; }
        else if (u < 57344) { W = Wm1  + (size_t)l*DD*D4; N = D4; off = u - 24576; }
        else                { W = Wm2  + (size_t)l*D4*DD; N = DD; off = u - 57344; }
    }
    int k2 = off / N, n = off - k2 * N;
    uint32_t h, l2;
    split_pair(W[(size_t)(2*k2) * N + n], W[(size_t)(2*k2+1) * N + n], h, l2);
    g_WH[idx] = h; g_WL[idx] = l2;
}

__global__ void adj_kernel(const float* __restrict__ A0, const float* __restrict__ P,
                           const float* __restrict__ Qm, const float* __restrict__ alphap,
                           float* __restrict__ A)
{
    int i = blockIdx.x, j = threadIdx.x;
    float a0 = A0[i*NN + j];
    float dot = 0.f;
    #pragma unroll
    for (int r = 0; r < 8; r++) dot += P[i*8 + r] * Qm[j*8 + r];
    float sp = (dot > 20.f) ? dot : log1pf(expf(dot));
    float ad = (a0 > 0.f) ? sp : 0.f;
    float a  = a0 * (1.f + alphap[0] * ad);
    __shared__ float sbuf[NN];
    sbuf[j] = a;
    __syncthreads();
    for (int st = 32; st >= 1; st >>= 1) {
        if (j < st) sbuf[j] += sbuf[j + st];
        __syncthreads();
    }
    A[i*NN + j] = a / (sbuf[0] + 1e-8f);
}

__global__ void pack_adj_kernel(const float* __restrict__ A)
{
    int idx = blockIdx.x * blockDim.x + threadIdx.x;
    if (idx >= NN*32) return;
    int i = idx >> 5, j2 = idx & 31;
    uint32_t h, l;
    split_pair(A[i*NN + 2*j2], A[i*NN + 2*j2 + 1], h, l);
    g_AJH[idx] = h; g_AJL[idx] = l;
}

__global__ void rowptr_kernel(const int* __restrict__ src, int E)
{
    int t = threadIdx.x;
    if (t > NN) return;
    int lo = 0, hi = E;
    while (lo < hi) { int mid = (lo + hi) >> 1; if (src[mid] < t) lo = mid + 1; else hi = mid; }
    g_rowptr[t] = lo;
}

__global__ void edge_kernel(const int* __restrict__ src, const int* __restrict__ dst,
                            const float* __restrict__ A0, int E)
{
    int e = blockIdx.x * blockDim.x + threadIdx.x;
    if (e < E) g_logA0[e] = logf(A0[src[e]*NN + dst[e]] + 1e-8f);
}

__global__ void copy_kernel(const float* __restrict__ src, float* __restrict__ dst, int n4)
{
    int i = blockIdx.x * blockDim.x + threadIdx.x;
    if (i < n4) ((float4*)dst)[i] = ((const float4*)src)[i];
}

__global__ void fill0_kernel(float* __restrict__ p, int n)
{
    int i = blockIdx.x * blockDim.x + threadIdx.x;
    if (i < n) p[i] = 0.f;
}

// ---------------- host driver ----------------
extern "C" void kernel_launch(void* const* d_in, const int* in_sizes, int n_in,
                              void* d_out, int out_size)
{
    const float* X     = (const float*)d_in[0];
    const float* Wp    = (const float*)d_in[1];
    const float* bp    = (const float*)d_in[2];
    const float* P     = (const float*)d_in[3];
    const float* Qm    = (const float*)d_in[4];
    const float* alpha = (const float*)d_in[5];
    const float* ln1g  = (const float*)d_in[6];
    const float* ln1b  = (const float*)d_in[7];
    const float* Wlin  = (const float*)d_in[8];
    const float* Wval  = (const float*)d_in[9];
    const float* a_att = (const float*)d_in[10];
    const float* Wout  = (const float*)d_in[11];
    const float* g1w   = (const float*)d_in[12];
    const float* g1b   = (const float*)d_in[13];
    const float* g2w   = (const float*)d_in[14];
    const float* g2b   = (const float*)d_in[15];
    const float* ln2g  = (const float*)d_in[16];
    const float* ln2b  = (const float*)d_in[17];
    const float* Wm1   = (const float*)d_in[18];
    const float* bm1   = (const float*)d_in[19];
    const float* Wm2   = (const float*)d_in[20];
    const float* bm2   = (const float*)d_in[21];
    const float* A0    = (const float*)d_in[22];
    const int*   srcI  = (const int*)d_in[24];
    const int*   dstI  = (const int*)d_in[25];
    int E = in_sizes[24];
    float* out = (float*)d_out;

    float *Z, *A;
    cudaGetSymbolAddress((void**)&Z, g_Z);
    cudaGetSymbolAddress((void**)&A, g_A);

    cudaFuncSetAttribute(fused_kernel, cudaFuncAttributeMaxDynamicSharedMemorySize,
                         SM_TOT * 4);

    const int ZN = NROWS * DD;
    const int SN = NBT * DD;
    const int AN = NN * NN;
    float* Zdst = (out_size >= ZN) ? out : Z;
    float* Sdst = (out_size >= ZN + SN) ? (out + ZN) : nullptr;

    pack_w_kernel<<<(WTOT + 255) / 256, 256>>>(Wp, Wlin, Wval, Wout, Wm1, Wm2);
    adj_kernel<<<NN, NN>>>(A0, P, Qm, alpha, A);
    pack_adj_kernel<<<(NN*32 + 255) / 256, 256>>>(A);
    rowptr_kernel<<<1, 128>>>(srcI, E);
    edge_kernel<<<(E + 127) / 128, 128>>>(srcI, dstI, A0, E);

    fused_kernel<<<NBT, 256, SM_TOT * 4>>>(
        X, bp, ln1g, ln1b, a_att, g1w, g1b, g2w, g2b,
        ln2g, ln2b, bm1, bm2, dstI, Zdst, Sdst);

    if (out_size >= ZN + SN + AN)
        copy_kernel<<<(AN / 4 + 255) / 256, 256>>>(A, out + ZN + SN, AN / 4);
    int tail = out_size - (ZN + SN + AN);
    if (tail > 0)
        fill0_kernel<<<(tail + 255) / 256, 256>>>(out + ZN + SN + AN, tail);
}

// round 15
// speedup vs baseline: 1.4018x; 1.1809x over previous
#include <cuda_runtime.h>
#include <math.h>
#include <stdint.h>

// ---------------- problem constants ----------------
#define NBT 512
#define NN 64
#define DD 128
#define HH 4
#define DHH 32
#define LL 3
#define D4 512
#define NROWS (NBT*NN)
#define MAXE 4096
#define TPB 512

// packed weights (u32; [K/2][N] k2-major), raw values (LN applied in-kernel)
#define WOFF_WP   0
#define WSEG      90112
#define WOFF_LIN(l)  (8192 + (l)*WSEG)
#define WOFF_VAL(l)  (8192 + (l)*WSEG + 8192)
#define WOFF_OUT(l)  (8192 + (l)*WSEG + 16384)
#define WOFF_M1(l)   (8192 + (l)*WSEG + 24576)
#define WOFF_M2(l)   (8192 + (l)*WSEG + 57344)
#define WTOT      (8192 + LL*WSEG)

// ---------------- device globals ----------------
__device__ float g_Z[NROWS*DD];
__device__ float g_A[NN*NN];
__device__ float g_logA0[MAXE];
__device__ int   g_rowptr[NN+1];
__device__ uint32_t g_WH[WTOT], g_WL[WTOT];
__device__ uint32_t g_AJH[NN*32], g_AJL[NN*32];

// ---------------- helpers ----------------
__device__ __forceinline__ uint32_t smem_u32(const void* p) {
    uint32_t a;
    asm("{ .reg .u64 t; cvta.to.shared.u64 t, %1; cvt.u32.u64 %0, t; }" : "=r"(a) : "l"(p));
    return a;
}
__device__ __forceinline__ void cp_async16(void* smem, const void* gmem) {
    unsigned sa = smem_u32(smem);
    asm volatile("cp.async.cg.shared.global [%0], [%1], 16;\n" :: "r"(sa), "l"(gmem));
}
__device__ __forceinline__ uint32_t pack_bf16x2(float x0, float x1) {
    uint32_t r;
    asm("cvt.rn.bf16x2.f32 %0, %1, %2;" : "=r"(r) : "f"(x1), "f"(x0));
    return r;
}
__device__ __forceinline__ void split_pair(float x0, float x1, uint32_t& h2, uint32_t& l2) {
    h2 = pack_bf16x2(x0, x1);
    float h0 = __uint_as_float(h2 << 16);
    float h1 = __uint_as_float(h2 & 0xffff0000u);
    l2 = pack_bf16x2(x0 - h0, x1 - h1);
}
__device__ __forceinline__ void mma_bf16(float* c, const uint32_t* a, const uint32_t* b) {
    asm volatile("mma.sync.aligned.m16n8k16.row.col.f32.bf16.bf16.f32 "
        "{%0,%1,%2,%3}, {%4,%5,%6,%7}, {%8,%9}, {%0,%1,%2,%3};"
        : "+f"(c[0]), "+f"(c[1]), "+f"(c[2]), "+f"(c[3])
        : "r"(a[0]), "r"(a[1]), "r"(a[2]), "r"(a[3]), "r"(b[0]), "r"(b[1]));
}

// ---------------- smem layout (4B units) ----------------
#define SM_Z    0          // 8192
#define SM_U    8192       // 8192
#define SM_XQ   16384      // 8256 (also XQu vertical-pack u32 / Qh in MLP)
#define SM_XV   24640      // 8256 (also XVu / Ql)
#define SM_PH   32896      // 4352 u32
#define SM_PL   37248      // 4352 u32
#define SM_AJH  41600      // 2304 u32
#define SM_AJL  43904      // 2304 u32
#define SM_WST  46208      // 3*2176 u32
#define SM_EXP  52736      // 1024
#define SM_DSTW 53760      // 1024 int
#define SM_SA   54784      // 128
#define SM_TOT  54912      // *4 = 219,648 B
#define XST 129
#define PST 68
#define AST 36

// ---------------- gemm: M=64, N=128, A resident (stride PST), B streamed ----
__device__ __forceinline__ void gemm_stream(
    const uint32_t* __restrict__ Ah, const uint32_t* __restrict__ Al,
    const uint32_t* __restrict__ Bh, const uint32_t* __restrict__ Bl,
    int bst, int ktiles, uint32_t* wst,
    float (&acc)[4][4], int tid, int lane, int wm, int wn)
{
    const int role = tid >> 8;            // 0: hi tile, 1: lo tile
    const int tt   = tid & 255;
    const int bk2  = tt >> 5;
    const int bc4  = (tt & 31) * 4;
    const uint32_t* Bsrc = role ? Bl : Bh;
    __syncthreads();
#define GISSUE(t) { \
        uint32_t* S_ = wst + ((t) % 3) * 2176 + role * 1088; \
        cp_async16(S_ + bk2*136 + bc4, Bsrc + (size_t)((t)*8 + bk2)*bst + bc4); \
        asm volatile("cp.async.commit_group;\n"); }
    GISSUE(0); GISSUE(1);
    for (int t = 0; t < ktiles; t++) {
        if (t < ktiles - 1) asm volatile("cp.async.wait_group 1;\n");
        else                asm volatile("cp.async.wait_group 0;\n");
        __syncthreads();
        if (t + 2 < ktiles) GISSUE(t + 2);
        const uint32_t* Sh = wst + (t % 3) * 2176;
        const uint32_t* Sl = Sh + 1088;
        const int r0 = wm + (lane >> 2);
        const int ka = t * 8 + (lane & 3);
        const int kb = lane & 3;
        uint32_t ah[4], al[4], bh[4][2], bl[4][2];
        ah[0] = Ah[r0*PST + ka];       ah[1] = Ah[(r0+8)*PST + ka];
        ah[2] = Ah[r0*PST + ka + 4];   ah[3] = Ah[(r0+8)*PST + ka + 4];
        al[0] = Al[r0*PST + ka];       al[1] = Al[(r0+8)*PST + ka];
        al[2] = Al[r0*PST + ka + 4];   al[3] = Al[(r0+8)*PST + ka + 4];
        const int bn0 = wn + (lane >> 2);
        #pragma unroll
        for (int ni = 0; ni < 4; ni++) {
            bh[ni][0] = Sh[kb*136 + bn0 + ni*8];
            bh[ni][1] = Sh[(kb+4)*136 + bn0 + ni*8];
            bl[ni][0] = Sl[kb*136 + bn0 + ni*8];
            bl[ni][1] = Sl[(kb+4)*136 + bn0 + ni*8];
        }
        #pragma unroll
        for (int ni = 0; ni < 4; ni++) {
            mma_bf16(acc[ni], al, bh[ni]);
            mma_bf16(acc[ni], ah, bl[ni]);
            mma_bf16(acc[ni], ah, bh[ni]);
        }
    }
#undef GISSUE
}

// ---------------- gemm with both operands resident (hmix) ----------------
__device__ __forceinline__ void gemm_resident(
    const uint32_t* __restrict__ Ah, const uint32_t* __restrict__ Al,
    const uint32_t* __restrict__ BhR, const uint32_t* __restrict__ BlR,
    int ktiles, float (&acc)[4][4], int lane, int wm, int wn)
{
    for (int t = 0; t < ktiles; t++) {
        const int r0 = wm + (lane >> 2);
        const int ka = t * 8 + (lane & 3);
        uint32_t ah[4], al[4], bh[4][2], bl[4][2];
        ah[0] = Ah[r0*AST + ka];       ah[1] = Ah[(r0+8)*AST + ka];
        ah[2] = Ah[r0*AST + ka + 4];   ah[3] = Ah[(r0+8)*AST + ka + 4];
        al[0] = Al[r0*AST + ka];       al[1] = Al[(r0+8)*AST + ka];
        al[2] = Al[r0*AST + ka + 4];   al[3] = Al[(r0+8)*AST + ka + 4];
        const int bn0 = wn + (lane >> 2);
        #pragma unroll
        for (int ni = 0; ni < 4; ni++) {
            bh[ni][0] = BhR[ka*136 + bn0 + ni*8];
            bh[ni][1] = BhR[(ka+4)*136 + bn0 + ni*8];
            bl[ni][0] = BlR[ka*136 + bn0 + ni*8];
            bl[ni][1] = BlR[(ka+4)*136 + bn0 + ni*8];
        }
        #pragma unroll
        for (int ni = 0; ni < 4; ni++) {
            mma_bf16(acc[ni], al, bh[ni]);
            mma_bf16(acc[ni], ah, bl[ni]);
            mma_bf16(acc[ni], ah, bh[ni]);
        }
    }
}

#define ZERO_ACC(a) { _Pragma("unroll") for (int ni_=0;ni_<4;ni_++) \
    _Pragma("unroll") for (int q_=0;q_<4;q_++) (a)[ni_][q_] = 0.f; }

// ---------------- fused per-bt kernel (512 threads) ----------------
extern __shared__ float smf[];
__global__ __launch_bounds__(TPB) void fused_kernel(
    const float* __restrict__ X, const float* __restrict__ bp,
    const float* __restrict__ ln1g, const float* __restrict__ ln1b,
    const float* __restrict__ a_att,
    const float* __restrict__ g1w, const float* __restrict__ g1b,
    const float* __restrict__ g2w, const float* __restrict__ g2b,
    const float* __restrict__ ln2g, const float* __restrict__ ln2b,
    const float* __restrict__ bm1, const float* __restrict__ bm2,
    const int* __restrict__ dstI,
    float* __restrict__ Zdst, float* __restrict__ Sdst)
{
    const int bt   = blockIdx.x;
    const int tid  = threadIdx.x;
    const int lane = tid & 31;
    const int wid  = tid >> 5;          // 0..15
    const int wm   = (wid & 3) * 16;
    const int wn   = (wid >> 2) * 32;

    float*    sZ  = smf + SM_Z;
    float*    sU  = smf + SM_U;
    float*    sXq = smf + SM_XQ;
    float*    sXv = smf + SM_XV;
    uint32_t* XQu = (uint32_t*)sXq;     // vertical-pack hi / MLP Qh
    uint32_t* XVu = (uint32_t*)sXv;     // vertical-pack lo / MLP Ql
    uint32_t* Ph  = (uint32_t*)(smf + SM_PH);
    uint32_t* Pl  = (uint32_t*)(smf + SM_PL);
    uint32_t* AJh = (uint32_t*)(smf + SM_AJH);
    uint32_t* AJl = (uint32_t*)(smf + SM_AJL);
    uint32_t* wst = (uint32_t*)(smf + SM_WST);
    float*    sexp  = smf + SM_EXP;
    int*      sdstW = (int*)(smf + SM_DSTW);
    float*    sa    = smf + SM_SA;

    // ---- adjacency resident (once) + input pack ----
    for (int idx = tid; idx < NN * 32; idx += TPB) {
        int i = idx >> 5, j2 = idx & 31;
        AJh[i*AST + j2] = g_AJH[idx];
        AJl[i*AST + j2] = g_AJL[idx];
    }
    {
        const float* Xb = X + (size_t)bt * NN * DD;
        for (int idx = tid; idx < 4096; idx += TPB) {
            int r = idx >> 6, p = idx & 63;
            float2 x = *(const float2*)(Xb + r * 128 + 2 * p);
            uint32_t h, l;
            split_pair(x.x, x.y, h, l);
            Ph[r * PST + p] = h; Pl[r * PST + p] = l;
        }
    }
    // proj: sZ = X@Wp + bp
    {
        float acc[4][4]; ZERO_ACC(acc);
        gemm_stream(Ph, Pl, g_WH + WOFF_WP, g_WL + WOFF_WP, 128, 8, wst,
                    acc, tid, lane, wm, wn);
        #pragma unroll
        for (int ni = 0; ni < 4; ni++)
            #pragma unroll
            for (int hf = 0; hf < 2; hf++) {
                int r = wm + hf*8 + (lane >> 2);
                int c = wn + ni*8 + 2*(lane & 3);
                sZ[r*128 + c]     = acc[ni][hf*2+0] + bp[c];
                sZ[r*128 + c + 1] = acc[ni][hf*2+1] + bp[c+1];
            }
    }
    __syncthreads();

    for (int l = 0; l < LL; l++) {
        // ---- LN1 + dual pack: horizontal -> Ph/Pl, vertical -> XQu/XVu ----
        {
            float4 g4 = *(const float4*)(ln1g + l*128 + lane*4);
            float4 b4 = *(const float4*)(ln1b + l*128 + lane*4);
            #pragma unroll
            for (int qp = 0; qp < 4; qp += 2) {
                int r0 = wid * 4 + qp;
                float4 x0 = ((const float4*)(sZ + r0*128))[lane];
                float4 x1 = ((const float4*)(sZ + (r0+1)*128))[lane];
                float s0 = x0.x+x0.y+x0.z+x0.w, q0 = x0.x*x0.x+x0.y*x0.y+x0.z*x0.z+x0.w*x0.w;
                float s1 = x1.x+x1.y+x1.z+x1.w, q1 = x1.x*x1.x+x1.y*x1.y+x1.z*x1.z+x1.w*x1.w;
                #pragma unroll
                for (int o = 16; o; o >>= 1) {
                    s0 += __shfl_xor_sync(0xffffffffu, s0, o);
                    q0 += __shfl_xor_sync(0xffffffffu, q0, o);
                    s1 += __shfl_xor_sync(0xffffffffu, s1, o);
                    q1 += __shfl_xor_sync(0xffffffffu, q1, o);
                }
                float m0 = s0*(1.f/128.f), rs0 = rsqrtf(q0*(1.f/128.f)-m0*m0+1e-5f);
                float m1 = s1*(1.f/128.f), rs1 = rsqrtf(q1*(1.f/128.f)-m1*m1+1e-5f);
                float4 h0, h1;
                h0.x=(x0.x-m0)*rs0*g4.x+b4.x; h0.y=(x0.y-m0)*rs0*g4.y+b4.y;
                h0.z=(x0.z-m0)*rs0*g4.z+b4.z; h0.w=(x0.w-m0)*rs0*g4.w+b4.w;
                h1.x=(x1.x-m1)*rs1*g4.x+b4.x; h1.y=(x1.y-m1)*rs1*g4.y+b4.y;
                h1.z=(x1.z-m1)*rs1*g4.z+b4.z; h1.w=(x1.w-m1)*rs1*g4.w+b4.w;
                uint32_t a, b;
                uint2 t2;
                split_pair(h0.x, h0.y, t2.x, a); split_pair(h0.z, h0.w, t2.y, b);
                *(uint2*)&Ph[r0*PST + lane*2] = t2;
                t2.x = a; t2.y = b;
                *(uint2*)&Pl[r0*PST + lane*2] = t2;
                split_pair(h1.x, h1.y, t2.x, a); split_pair(h1.z, h1.w, t2.y, b);
                *(uint2*)&Ph[(r0+1)*PST + lane*2] = t2;
                t2.x = a; t2.y = b;
                *(uint2*)&Pl[(r0+1)*PST + lane*2] = t2;
                // vertical: pair rows r0, r0+1
                uint4 vh, vl;
                split_pair(h0.x, h1.x, vh.x, vl.x);
                split_pair(h0.y, h1.y, vh.y, vl.y);
                split_pair(h0.z, h1.z, vh.z, vl.z);
                split_pair(h0.w, h1.w, vh.w, vl.w);
                int j2 = r0 >> 1;
                *(uint4*)&XQu[j2*136 + lane*4] = vh;
                *(uint4*)&XVu[j2*136 + lane*4] = vl;
            }
            if (tid < 128) sa[tid] = a_att[l*128 + tid];
        }
        __syncthreads();

        // ---- hmix: sU = sZ + A@Hn ----
        {
            float acc[4][4]; ZERO_ACC(acc);
            gemm_resident(AJh, AJl, XQu, XVu, 4, acc, lane, wm, wn);
            #pragma unroll
            for (int ni = 0; ni < 4; ni++)
                #pragma unroll
                for (int hf = 0; hf < 2; hf++) {
                    int r = wm + hf*8 + (lane >> 2);
                    int c = wn + ni*8 + 2*(lane & 3);
                    sU[r*128 + c]     = sZ[r*128 + c]     + acc[ni][hf*2+0];
                    sU[r*128 + c + 1] = sZ[r*128 + c + 1] + acc[ni][hf*2+1];
                }
        }
        __syncthreads();   // all hmix reads of XQu/XVu done before Xq overwrites

        // ---- Xq / Xv gemms (A = Ph horizontal Hn) ----
        for (int qv = 0; qv < 2; qv++) {
            float acc[4][4]; ZERO_ACC(acc);
            int off = qv ? WOFF_VAL(l) : WOFF_LIN(l);
            gemm_stream(Ph, Pl, g_WH + off, g_WL + off, 128, 8, wst,
                        acc, tid, lane, wm, wn);
            float* dst = qv ? sXv : sXq;
            #pragma unroll
            for (int ni = 0; ni < 4; ni++)
                #pragma unroll
                for (int hf = 0; hf < 2; hf++) {
                    int r = wm + hf*8 + (lane >> 2);
                    int c = wn + ni*8 + 2*(lane & 3);
                    dst[r*XST + c]     = acc[ni][hf*2+0];
                    dst[r*XST + c + 1] = acc[ni][hf*2+1];
                }
        }
        __syncthreads();

        // ---- attention: warp = (head, quarter); Y packed -> Ph/Pl ----
        {
            const int h = wid & 3;
            const int quarter = wid >> 2;
            float* myexp = sexp + wid * 64;
            int*   mydst = sdstW + wid * 64;
            for (int i = quarter; i < NN; i += 4) {
                const int e0  = g_rowptr[i];
                const int deg = g_rowptr[i+1] - e0;
                const float* qrow = sXq + i*XST + h*32;
                float vmax = -1e30f;
                for (int kb = 0; kb < deg; kb += 32) {
                    const int k = kb + lane;
                    const bool ok = (k < deg);
                    const int j = ok ? dstI[e0 + k] : 0;
                    const float* jrow = sXq + j*XST + h*32;
                    float accd = 0.f;
                    #pragma unroll
                    for (int d = 0; d < 32; d++) {
                        float x = qrow[d] + jrow[d];
                        x = (x > 0.f) ? x : 0.2f * x;
                        accd = fmaf(x, sa[h*32 + d], accd);
                    }
                    float v = ok ? (accd + g_logA0[e0 + k]) : -1e30f;
                    if (ok) { myexp[k] = v; mydst[k] = j; }
                    vmax = fmaxf(vmax, v);
                }
                #pragma unroll
                for (int o = 16; o; o >>= 1)
                    vmax = fmaxf(vmax, __shfl_xor_sync(0xffffffffu, vmax, o));
                __syncwarp();
                float den = 0.f;
                for (int kb = 0; kb < deg; kb += 32) {
                    const int k = kb + lane;
                    if (k < deg) {
                        float ev = expf(myexp[k] - vmax);
                        myexp[k] = ev;
                        den += ev;
                    }
                }
                #pragma unroll
                for (int o = 16; o; o >>= 1) den += __shfl_xor_sync(0xffffffffu, den, o);
                __syncwarp();
                const float inv = 1.f / den;
                float y = 0.f;
                #pragma unroll 4
                for (int k = 0; k < deg; k++)
                    y = fmaf(myexp[k], sXv[mydst[k]*XST + h*32 + lane], y);
                float yf = y * inv;
                float yp = __shfl_down_sync(0xffffffffu, yf, 1);
                if (!(lane & 1)) {
                    uint32_t hh, ll;
                    split_pair(yf, yp, hh, ll);
                    Ph[i*PST + h*16 + (lane >> 1)] = hh;
                    Pl[i*PST + h*16 + (lane >> 1)] = ll;
                }
                __syncwarp();
            }
        }

        // ---- Wout gemm: sU += Y@Wout ----
        {
            float acc[4][4]; ZERO_ACC(acc);
            gemm_stream(Ph, Pl, g_WH + WOFF_OUT(l), g_WL + WOFF_OUT(l), 128, 8, wst,
                        acc, tid, lane, wm, wn);
            #pragma unroll
            for (int ni = 0; ni < 4; ni++)
                #pragma unroll
                for (int hf = 0; hf < 2; hf++) {
                    int r = wm + hf*8 + (lane >> 2);
                    int c = wn + ni*8 + 2*(lane & 3);
                    sU[r*128 + c]     += acc[ni][hf*2+0];
                    sU[r*128 + c + 1] += acc[ni][hf*2+1];
                }
        }
        __syncthreads();

        // ---- gate + LN2 -> sU gated (in place); packed LN2 -> Ph/Pl ----
        {
            float4 w1v = *(const float4*)(g1w + l*128 + lane*4);
            float4 b1v = *(const float4*)(g1b + l*128 + lane*4);
            float4 w2v = *(const float4*)(g2w + l*128 + lane*4);
            float4 l2g = *(const float4*)(ln2g + l*128 + lane*4);
            float4 l2b = *(const float4*)(ln2b + l*128 + lane*4);
            float g2bs = g2b[l];
            #pragma unroll
            for (int q = 0; q < 4; q++) {
                int r = wid * 4 + q;
                float4* u4 = (float4*)(sU + r*128);
                float4 x = u4[lane];
                float s  = x.x + x.y + x.z + x.w;
                float ss = x.x*x.x + x.y*x.y + x.z*x.z + x.w*x.w;
                #pragma unroll
                for (int o = 16; o; o >>= 1) {
                    s  += __shfl_xor_sync(0xffffffffu, s,  o);
                    ss += __shfl_xor_sync(0xffffffffu, ss, o);
                }
                float m   = s * (1.f/128.f);
                float var = ss * (1.f/128.f) - m*m;
                float accg = 0.f;
                {
                    float t0 = m*w1v.x + b1v.x; accg += (t0/(1.f+expf(-t0)))*w2v.x;
                    float t1 = m*w1v.y + b1v.y; accg += (t1/(1.f+expf(-t1)))*w2v.y;
                    float t2 = m*w1v.z + b1v.z; accg += (t2/(1.f+expf(-t2)))*w2v.z;
                    float t3 = m*w1v.w + b1v.w; accg += (t3/(1.f+expf(-t3)))*w2v.w;
                }
                #pragma unroll
                for (int o = 16; o; o >>= 1) accg += __shfl_xor_sync(0xffffffffu, accg, o);
                float gate = 1.f / (1.f + expf(-(accg + g2bs)));
                float4 vg; vg.x = x.x*gate; vg.y = x.y*gate; vg.z = x.z*gate; vg.w = x.w*gate;
                u4[lane] = vg;
                float mu2 = m * gate;
                float rsg = rsqrtf(var * gate * gate + 1e-5f);
                float4 hn;
                hn.x = (vg.x - mu2)*rsg*l2g.x + l2b.x;
                hn.y = (vg.y - mu2)*rsg*l2g.y + l2b.y;
                hn.z = (vg.z - mu2)*rsg*l2g.z + l2b.z;
                hn.w = (vg.w - mu2)*rsg*l2g.w + l2b.w;
                uint2 t2p; uint32_t a, b;
                split_pair(hn.x, hn.y, t2p.x, a); split_pair(hn.z, hn.w, t2p.y, b);
                *(uint2*)&Ph[r*PST + lane*2] = t2p;
                t2p.x = a; t2p.y = b;
                *(uint2*)&Pl[r*PST + lane*2] = t2p;
            }
        }
        __syncthreads();

        // ---- MLP (chunked): Z = silu(LN2@Wm1+bm1)@Wm2 + bm2 + Ug ----
        {
            float accZ[4][4]; ZERO_ACC(accZ);
            for (int ch = 0; ch < 4; ch++) {
                float accM[4][4]; ZERO_ACC(accM);
                gemm_stream(Ph, Pl,
                            g_WH + WOFF_M1(l) + ch*128, g_WL + WOFF_M1(l) + ch*128,
                            512, 8, wst, accM, tid, lane, wm, wn);
                #pragma unroll
                for (int ni = 0; ni < 4; ni++)
                    #pragma unroll
                    for (int hf = 0; hf < 2; hf++) {
                        int r = wm + hf*8 + (lane >> 2);
                        int c = wn + ni*8 + 2*(lane & 3);
                        float v0 = accM[ni][hf*2+0] + bm1[l*512 + ch*128 + c];
                        float v1 = accM[ni][hf*2+1] + bm1[l*512 + ch*128 + c + 1];
                        v0 = v0 / (1.f + expf(-v0));
                        v1 = v1 / (1.f + expf(-v1));
                        uint32_t h, lo;
                        split_pair(v0, v1, h, lo);
                        XQu[r*PST + (c >> 1)] = h;
                        XVu[r*PST + (c >> 1)] = lo;
                    }
                gemm_stream(XQu, XVu,
                            g_WH + WOFF_M2(l) + (size_t)(ch*64)*128,
                            g_WL + WOFF_M2(l) + (size_t)(ch*64)*128,
                            128, 8, wst, accZ, tid, lane, wm, wn);
            }
            __syncthreads();
            #pragma unroll
            for (int ni = 0; ni < 4; ni++)
                #pragma unroll
                for (int hf = 0; hf < 2; hf++) {
                    int r = wm + hf*8 + (lane >> 2);
                    int c = wn + ni*8 + 2*(lane & 3);
                    sZ[r*128 + c]     = accZ[ni][hf*2+0] + bm2[l*128 + c]     + sU[r*128 + c];
                    sZ[r*128 + c + 1] = accZ[ni][hf*2+1] + bm2[l*128 + c + 1] + sU[r*128 + c + 1];
                }
        }
        __syncthreads();
    }

    // ---- outputs ----
    {
        float4* zo = (float4*)(Zdst + (size_t)bt * NN * DD);
        const float4* zs = (const float4*)sZ;
        for (int idx = tid; idx < 2048; idx += TPB) zo[idx] = zs[idx];
        if (Sdst) {
            int d = tid & 127, part = tid >> 7;
            float ps = 0.f;
            for (int i = part*16; i < part*16 + 16; i++) ps += sZ[i*128 + d];
            sexp[part*128 + d] = ps;
            __syncthreads();
            if (tid < 128)
                Sdst[(size_t)bt*128 + tid] =
                    (sexp[tid] + sexp[128+tid] + sexp[256+tid] + sexp[384+tid]) * (1.f/64.f);
        }
    }
}

// ---------------- setup kernels ----------------
__global__ void pack_w_kernel(
    const float* __restrict__ Wp, const float* __restrict__ Wlin,
    const float* __restrict__ Wval, const float* __restrict__ Wout,
    const float* __restrict__ Wm1, const float* __restrict__ Wm2)
{
    int idx = blockIdx.x * blockDim.x + threadIdx.x;
    if (idx >= WTOT) return;
    const float* W; int N, off;
    if (idx < 8192) { W = Wp; N = DD; off = idx; }
    else {
        int j = idx - 8192, l = j / WSEG, u = j % WSEG;
        if (u < 8192)       { W = Wlin + (size_t)l*DD*DD; N = DD; off = u; }
        else if (u < 16384) { W = Wval + (size_t)l*DD*DD; N = DD; off = u - 8192; }
        else if (u < 24576) { W = Wout + (size_t)l*DD*DD; N = DD; off = u - 16384; }
        else if (u < 57344) { W = Wm1  + (size_t)l*DD*D4; N = D4; off = u - 24576; }
        else                { W = Wm2  + (size_t)l*D4*DD; N = DD; off = u - 57344; }
    }
    int k2 = off / N, n = off - k2 * N;
    uint32_t h, l2;
    split_pair(W[(size_t)(2*k2) * N + n], W[(size_t)(2*k2+1) * N + n], h, l2);
    g_WH[idx] = h; g_WL[idx] = l2;
}

__global__ void adj_kernel(const float* __restrict__ A0, const float* __restrict__ P,
                           const float* __restrict__ Qm, const float* __restrict__ alphap,
                           float* __restrict__ A)
{
    int i = blockIdx.x, j = threadIdx.x;
    float a0 = A0[i*NN + j];
    float dot = 0.f;
    #pragma unroll
    for (int r = 0; r < 8; r++) dot += P[i*8 + r] * Qm[j*8 + r];
    float sp = (dot > 20.f) ? dot : log1pf(expf(dot));
    float ad = (a0 > 0.f) ? sp : 0.f;
    float a  = a0 * (1.f + alphap[0] * ad);
    __shared__ float sbuf[NN];
    sbuf[j] = a;
    __syncthreads();
    for (int st = 32; st >= 1; st >>= 1) {
        if (j < st) sbuf[j] += sbuf[j + st];
        __syncthreads();
    }
    A[i*NN + j] = a / (sbuf[0] + 1e-8f);
}

__global__ void pack_adj_kernel(const float* __restrict__ A)
{
    int idx = blockIdx.x * blockDim.x + threadIdx.x;
    if (idx >= NN*32) return;
    int i = idx >> 5, j2 = idx & 31;
    uint32_t h, l;
    split_pair(A[i*NN + 2*j2], A[i*NN + 2*j2 + 1], h, l);
    g_AJH[idx] = h; g_AJL[idx] = l;
}

__global__ void rowptr_kernel(const int* __restrict__ src, int E)
{
    int t = threadIdx.x;
    if (t > NN) return;
    int lo = 0, hi = E;
    while (lo < hi) { int mid = (lo + hi) >> 1; if (src[mid] < t) lo = mid + 1; else hi = mid; }
    g_rowptr[t] = lo;
}

__global__ void edge_kernel(const int* __restrict__ src, const int* __restrict__ dst,
                            const float* __restrict__ A0, int E)
{
    int e = blockIdx.x * blockDim.x + threadIdx.x;
    if (e < E) g_logA0[e] = logf(A0[src[e]*NN + dst[e]] + 1e-8f);
}

__global__ void copy_kernel(const float* __restrict__ src, float* __restrict__ dst, int n4)
{
    int i = blockIdx.x * blockDim.x + threadIdx.x;
    if (i < n4) ((float4*)dst)[i] = ((const float4*)src)[i];
}

__global__ void fill0_kernel(float* __restrict__ p, int n)
{
    int i = blockIdx.x * blockDim.x + threadIdx.x;
    if (i < n) p[i] = 0.f;
}

// ---------------- host driver ----------------
extern "C" void kernel_launch(void* const* d_in, const int* in_sizes, int n_in,
                              void* d_out, int out_size)
{
    const float* X     = (const float*)d_in[0];
    const float* Wp    = (const float*)d_in[1];
    const float* bp    = (const float*)d_in[2];
    const float* P     = (const float*)d_in[3];
    const float* Qm    = (const float*)d_in[4];
    const float* alpha = (const float*)d_in[5];
    const float* ln1g  = (const float*)d_in[6];
    const float* ln1b  = (const float*)d_in[7];
    const float* Wlin  = (const float*)d_in[8];
    const float* Wval  = (const float*)d_in[9];
    const float* a_att = (const float*)d_in[10];
    const float* Wout  = (const float*)d_in[11];
    const float* g1w   = (const float*)d_in[12];
    const float* g1b   = (const float*)d_in[13];
    const float* g2w   = (const float*)d_in[14];
    const float* g2b   = (const float*)d_in[15];
    const float* ln2g  = (const float*)d_in[16];
    const float* ln2b  = (const float*)d_in[17];
    const float* Wm1   = (const float*)d_in[18];
    const float* bm1   = (const float*)d_in[19];
    const float* Wm2   = (const float*)d_in[20];
    const float* bm2   = (const float*)d_in[21];
    const float* A0    = (const float*)d_in[22];
    const int*   srcI  = (const int*)d_in[24];
    const int*   dstI  = (const int*)d_in[25];
    int E = in_sizes[24];
    float* out = (float*)d_out;

    float *Z, *A;
    cudaGetSymbolAddress((void**)&Z, g_Z);
    cudaGetSymbolAddress((void**)&A, g_A);

    cudaFuncSetAttribute(fused_kernel, cudaFuncAttributeMaxDynamicSharedMemorySize,
                         SM_TOT * 4);

    const int ZN = NROWS * DD;
    const int SN = NBT * DD;
    const int AN = NN * NN;
    float* Zdst = (out_size >= ZN) ? out : Z;
    float* Sdst = (out_size >= ZN + SN) ? (out + ZN) : nullptr;

    pack_w_kernel<<<(WTOT + 255) / 256, 256>>>(Wp, Wlin, Wval, Wout, Wm1, Wm2);
    adj_kernel<<<NN, NN>>>(A0, P, Qm, alpha, A);
    pack_adj_kernel<<<(NN*32 + 255) / 256, 256>>>(A);
    rowptr_kernel<<<1, 128>>>(srcI, E);
    edge_kernel<<<(E + 127) / 128, 128>>>(srcI, dstI, A0, E);

    fused_kernel<<<NBT, TPB, SM_TOT * 4>>>(
        X, bp, ln1g, ln1b, a_att, g1w, g1b, g2w, g2b,
        ln2g, ln2b, bm1, bm2, dstI, Zdst, Sdst);

    if (out_size >= ZN + SN + AN)
        copy_kernel<<<(AN / 4 + 255) / 256, 256>>>(A, out + ZN + SN, AN / 4);
    int tail = out_size - (ZN + SN + AN);
    if (tail > 0)
        fill0_kernel<<<(tail + 255) / 256, 256>>>(out + ZN + SN + AN, tail);
}

// round 16
// speedup vs baseline: 1.4038x; 1.0014x over previous
#include <cuda_runtime.h>
#include <math.h>
#include <stdint.h>

// ---------------- problem constants ----------------
#define NBT 512
#define NN 64
#define DD 128
#define HH 4
#define DHH 32
#define LL 3
#define D4 512
#define NROWS (NBT*NN)
#define MAXE 4096
#define TPB 512

// packed weights (u32; [K/2][N] k2-major), raw values (LN applied in-kernel)
#define WOFF_WP   0
#define WSEG      90112
#define WOFF_LIN(l)  (8192 + (l)*WSEG)
#define WOFF_VAL(l)  (8192 + (l)*WSEG + 8192)
#define WOFF_OUT(l)  (8192 + (l)*WSEG + 16384)
#define WOFF_M1(l)   (8192 + (l)*WSEG + 24576)
#define WOFF_M2(l)   (8192 + (l)*WSEG + 57344)
#define WTOT      (8192 + LL*WSEG)

// ---------------- device globals ----------------
__device__ float g_Z[NROWS*DD];
__device__ float g_A[NN*NN];
__device__ float g_logA0[MAXE];
__device__ int   g_rowptr[NN+1];
__device__ uint32_t g_WH[WTOT], g_WL[WTOT];
__device__ uint32_t g_AJH[NN*32], g_AJL[NN*32];

// ---------------- helpers ----------------
__device__ __forceinline__ uint32_t smem_u32(const void* p) {
    uint32_t a;
    asm("{ .reg .u64 t; cvta.to.shared.u64 t, %1; cvt.u32.u64 %0, t; }" : "=r"(a) : "l"(p));
    return a;
}
__device__ __forceinline__ void cp_async16(void* smem, const void* gmem) {
    unsigned sa = smem_u32(smem);
    asm volatile("cp.async.cg.shared.global [%0], [%1], 16;\n" :: "r"(sa), "l"(gmem));
}
__device__ __forceinline__ uint32_t pack_bf16x2(float x0, float x1) {
    uint32_t r;
    asm("cvt.rn.bf16x2.f32 %0, %1, %2;" : "=r"(r) : "f"(x1), "f"(x0));
    return r;
}
__device__ __forceinline__ void split_pair(float x0, float x1, uint32_t& h2, uint32_t& l2) {
    h2 = pack_bf16x2(x0, x1);
    float h0 = __uint_as_float(h2 << 16);
    float h1 = __uint_as_float(h2 & 0xffff0000u);
    l2 = pack_bf16x2(x0 - h0, x1 - h1);
}
__device__ __forceinline__ void mma_bf16(float* c, const uint32_t* a, const uint32_t* b) {
    asm volatile("mma.sync.aligned.m16n8k16.row.col.f32.bf16.bf16.f32 "
        "{%0,%1,%2,%3}, {%4,%5,%6,%7}, {%8,%9}, {%0,%1,%2,%3};"
        : "+f"(c[0]), "+f"(c[1]), "+f"(c[2]), "+f"(c[3])
        : "r"(a[0]), "r"(a[1]), "r"(a[2]), "r"(a[3]), "r"(b[0]), "r"(b[1]));
}

// ---------------- smem layout (4B units) ----------------
#define SM_Z    0          // 8192
#define SM_U    8192       // 8192
#define SM_XQ   16384      // 8256 (also XQu vertical-pack u32 / Qh in MLP)
#define SM_XV   24640      // 8256 (also XVu / Ql)
#define SM_PH   32896      // 4352 u32
#define SM_PL   37248      // 4352 u32
#define SM_AJH  41600      // 2304 u32
#define SM_AJL  43904      // 2304 u32
#define SM_WST  46208      // 3*2176 u32
#define SM_EXP  52736      // 1024
#define SM_DSTW 53760      // 1024 int
#define SM_SA   54784      // 128
#define SM_TOT  54912      // *4 = 219,648 B
#define XST 129
#define PST 68
#define AST 36

// ---------------- gemm: M=64, N=128, A resident (stride PST), B streamed ----
__device__ __forceinline__ void gemm_stream(
    const uint32_t* __restrict__ Ah, const uint32_t* __restrict__ Al,
    const uint32_t* __restrict__ Bh, const uint32_t* __restrict__ Bl,
    int bst, int ktiles, uint32_t* wst,
    float (&acc)[4][4], int tid, int lane, int wm, int wn)
{
    const int role = tid >> 8;            // 0: hi tile, 1: lo tile
    const int tt   = tid & 255;
    const int bk2  = tt >> 5;
    const int bc4  = (tt & 31) * 4;
    const uint32_t* Bsrc = role ? Bl : Bh;
    __syncthreads();
#define GISSUE(t) { \
        uint32_t* S_ = wst + ((t) % 3) * 2176 + role * 1088; \
        cp_async16(S_ + bk2*136 + bc4, Bsrc + (size_t)((t)*8 + bk2)*bst + bc4); \
        asm volatile("cp.async.commit_group;\n"); }
    GISSUE(0); GISSUE(1);
    for (int t = 0; t < ktiles; t++) {
        if (t < ktiles - 1) asm volatile("cp.async.wait_group 1;\n");
        else                asm volatile("cp.async.wait_group 0;\n");
        __syncthreads();
        if (t + 2 < ktiles) GISSUE(t + 2);
        const uint32_t* Sh = wst + (t % 3) * 2176;
        const uint32_t* Sl = Sh + 1088;
        const int r0 = wm + (lane >> 2);
        const int ka = t * 8 + (lane & 3);
        const int kb = lane & 3;
        uint32_t ah[4], al[4], bh[4][2], bl[4][2];
        ah[0] = Ah[r0*PST + ka];       ah[1] = Ah[(r0+8)*PST + ka];
        ah[2] = Ah[r0*PST + ka + 4];   ah[3] = Ah[(r0+8)*PST + ka + 4];
        al[0] = Al[r0*PST + ka];       al[1] = Al[(r0+8)*PST + ka];
        al[2] = Al[r0*PST + ka + 4];   al[3] = Al[(r0+8)*PST + ka + 4];
        const int bn0 = wn + (lane >> 2);
        #pragma unroll
        for (int ni = 0; ni < 4; ni++) {
            bh[ni][0] = Sh[kb*136 + bn0 + ni*8];
            bh[ni][1] = Sh[(kb+4)*136 + bn0 + ni*8];
            bl[ni][0] = Sl[kb*136 + bn0 + ni*8];
            bl[ni][1] = Sl[(kb+4)*136 + bn0 + ni*8];
        }
        #pragma unroll
        for (int ni = 0; ni < 4; ni++) {
            mma_bf16(acc[ni], al, bh[ni]);
            mma_bf16(acc[ni], ah, bl[ni]);
            mma_bf16(acc[ni], ah, bh[ni]);
        }
    }
#undef GISSUE
}

// ---------------- gemm with both operands resident (hmix) ----------------
__device__ __forceinline__ void gemm_resident(
    const uint32_t* __restrict__ Ah, const uint32_t* __restrict__ Al,
    const uint32_t* __restrict__ BhR, const uint32_t* __restrict__ BlR,
    int ktiles, float (&acc)[4][4], int lane, int wm, int wn)
{
    for (int t = 0; t < ktiles; t++) {
        const int r0 = wm + (lane >> 2);
        const int ka = t * 8 + (lane & 3);
        uint32_t ah[4], al[4], bh[4][2], bl[4][2];
        ah[0] = Ah[r0*AST + ka];       ah[1] = Ah[(r0+8)*AST + ka];
        ah[2] = Ah[r0*AST + ka + 4];   ah[3] = Ah[(r0+8)*AST + ka + 4];
        al[0] = Al[r0*AST + ka];       al[1] = Al[(r0+8)*AST + ka];
        al[2] = Al[r0*AST + ka + 4];   al[3] = Al[(r0+8)*AST + ka + 4];
        const int bn0 = wn + (lane >> 2);
        #pragma unroll
        for (int ni = 0; ni < 4; ni++) {
            bh[ni][0] = BhR[ka*136 + bn0 + ni*8];
            bh[ni][1] = BhR[(ka+4)*136 + bn0 + ni*8];
            bl[ni][0] = BlR[ka*136 + bn0 + ni*8];
            bl[ni][1] = BlR[(ka+4)*136 + bn0 + ni*8];
        }
        #pragma unroll
        for (int ni = 0; ni < 4; ni++) {
            mma_bf16(acc[ni], al, bh[ni]);
            mma_bf16(acc[ni], ah, bl[ni]);
            mma_bf16(acc[ni], ah, bh[ni]);
        }
    }
}

#define ZERO_ACC(a) { _Pragma("unroll") for (int ni_=0;ni_<4;ni_++) \
    _Pragma("unroll") for (int q_=0;q_<4;q_++) (a)[ni_][q_] = 0.f; }

// ---------------- fused per-bt kernel (512 threads) ----------------
extern __shared__ float smf[];
__global__ __launch_bounds__(TPB) void fused_kernel(
    const float* __restrict__ X, const float* __restrict__ bp,
    const float* __restrict__ ln1g, const float* __restrict__ ln1b,
    const float* __restrict__ a_att,
    const float* __restrict__ g1w, const float* __restrict__ g1b,
    const float* __restrict__ g2w, const float* __restrict__ g2b,
    const float* __restrict__ ln2g, const float* __restrict__ ln2b,
    const float* __restrict__ bm1, const float* __restrict__ bm2,
    const int* __restrict__ dstI,
    float* __restrict__ Zdst, float* __restrict__ Sdst)
{
    const int bt   = blockIdx.x;
    const int tid  = threadIdx.x;
    const int lane = tid & 31;
    const int wid  = tid >> 5;          // 0..15
    const int wm   = (wid & 3) * 16;
    const int wn   = (wid >> 2) * 32;

    float*    sZ  = smf + SM_Z;
    float*    sU  = smf + SM_U;
    float*    sXq = smf + SM_XQ;
    float*    sXv = smf + SM_XV;
    uint32_t* XQu = (uint32_t*)sXq;     // vertical-pack hi / MLP Qh
    uint32_t* XVu = (uint32_t*)sXv;     // vertical-pack lo / MLP Ql
    uint32_t* Ph  = (uint32_t*)(smf + SM_PH);
    uint32_t* Pl  = (uint32_t*)(smf + SM_PL);
    uint32_t* AJh = (uint32_t*)(smf + SM_AJH);
    uint32_t* AJl = (uint32_t*)(smf + SM_AJL);
    uint32_t* wst = (uint32_t*)(smf + SM_WST);
    float*    sexp  = smf + SM_EXP;
    int*      sdstW = (int*)(smf + SM_DSTW);
    float*    sa    = smf + SM_SA;

    // ---- adjacency resident (once) + input pack ----
    for (int idx = tid; idx < NN * 32; idx += TPB) {
        int i = idx >> 5, j2 = idx & 31;
        AJh[i*AST + j2] = g_AJH[idx];
        AJl[i*AST + j2] = g_AJL[idx];
    }
    {
        const float* Xb = X + (size_t)bt * NN * DD;
        for (int idx = tid; idx < 4096; idx += TPB) {
            int r = idx >> 6, p = idx & 63;
            float2 x = *(const float2*)(Xb + r * 128 + 2 * p);
            uint32_t h, l;
            split_pair(x.x, x.y, h, l);
            Ph[r * PST + p] = h; Pl[r * PST + p] = l;
        }
    }
    // proj: sZ = X@Wp + bp
    {
        float acc[4][4]; ZERO_ACC(acc);
        gemm_stream(Ph, Pl, g_WH + WOFF_WP, g_WL + WOFF_WP, 128, 8, wst,
                    acc, tid, lane, wm, wn);
        #pragma unroll
        for (int ni = 0; ni < 4; ni++)
            #pragma unroll
            for (int hf = 0; hf < 2; hf++) {
                int r = wm + hf*8 + (lane >> 2);
                int c = wn + ni*8 + 2*(lane & 3);
                sZ[r*128 + c]     = acc[ni][hf*2+0] + bp[c];
                sZ[r*128 + c + 1] = acc[ni][hf*2+1] + bp[c+1];
            }
    }
    __syncthreads();

    for (int l = 0; l < LL; l++) {
        // ---- LN1 + dual pack: horizontal -> Ph/Pl, vertical -> XQu/XVu ----
        {
            float4 g4 = *(const float4*)(ln1g + l*128 + lane*4);
            float4 b4 = *(const float4*)(ln1b + l*128 + lane*4);
            #pragma unroll
            for (int qp = 0; qp < 4; qp += 2) {
                int r0 = wid * 4 + qp;
                float4 x0 = ((const float4*)(sZ + r0*128))[lane];
                float4 x1 = ((const float4*)(sZ + (r0+1)*128))[lane];
                float s0 = x0.x+x0.y+x0.z+x0.w, q0 = x0.x*x0.x+x0.y*x0.y+x0.z*x0.z+x0.w*x0.w;
                float s1 = x1.x+x1.y+x1.z+x1.w, q1 = x1.x*x1.x+x1.y*x1.y+x1.z*x1.z+x1.w*x1.w;
                #pragma unroll
                for (int o = 16; o; o >>= 1) {
                    s0 += __shfl_xor_sync(0xffffffffu, s0, o);
                    q0 += __shfl_xor_sync(0xffffffffu, q0, o);
                    s1 += __shfl_xor_sync(0xffffffffu, s1, o);
                    q1 += __shfl_xor_sync(0xffffffffu, q1, o);
                }
                float m0 = s0*(1.f/128.f), rs0 = rsqrtf(q0*(1.f/128.f)-m0*m0+1e-5f);
                float m1 = s1*(1.f/128.f), rs1 = rsqrtf(q1*(1.f/128.f)-m1*m1+1e-5f);
                float4 h0, h1;
                h0.x=(x0.x-m0)*rs0*g4.x+b4.x; h0.y=(x0.y-m0)*rs0*g4.y+b4.y;
                h0.z=(x0.z-m0)*rs0*g4.z+b4.z; h0.w=(x0.w-m0)*rs0*g4.w+b4.w;
                h1.x=(x1.x-m1)*rs1*g4.x+b4.x; h1.y=(x1.y-m1)*rs1*g4.y+b4.y;
                h1.z=(x1.z-m1)*rs1*g4.z+b4.z; h1.w=(x1.w-m1)*rs1*g4.w+b4.w;
                uint32_t a, b;
                uint2 t2;
                split_pair(h0.x, h0.y, t2.x, a); split_pair(h0.z, h0.w, t2.y, b);
                *(uint2*)&Ph[r0*PST + lane*2] = t2;
                t2.x = a; t2.y = b;
                *(uint2*)&Pl[r0*PST + lane*2] = t2;
                split_pair(h1.x, h1.y, t2.x, a); split_pair(h1.z, h1.w, t2.y, b);
                *(uint2*)&Ph[(r0+1)*PST + lane*2] = t2;
                t2.x = a; t2.y = b;
                *(uint2*)&Pl[(r0+1)*PST + lane*2] = t2;
                // vertical: pair rows r0, r0+1
                uint4 vh, vl;
                split_pair(h0.x, h1.x, vh.x, vl.x);
                split_pair(h0.y, h1.y, vh.y, vl.y);
                split_pair(h0.z, h1.z, vh.z, vl.z);
                split_pair(h0.w, h1.w, vh.w, vl.w);
                int j2 = r0 >> 1;
                *(uint4*)&XQu[j2*136 + lane*4] = vh;
                *(uint4*)&XVu[j2*136 + lane*4] = vl;
            }
            if (tid < 128) sa[tid] = a_att[l*128 + tid];
        }
        __syncthreads();

        // ---- hmix: sU = sZ + A@Hn ----
        {
            float acc[4][4]; ZERO_ACC(acc);
            gemm_resident(AJh, AJl, XQu, XVu, 4, acc, lane, wm, wn);
            #pragma unroll
            for (int ni = 0; ni < 4; ni++)
                #pragma unroll
                for (int hf = 0; hf < 2; hf++) {
                    int r = wm + hf*8 + (lane >> 2);
                    int c = wn + ni*8 + 2*(lane & 3);
                    sU[r*128 + c]     = sZ[r*128 + c]     + acc[ni][hf*2+0];
                    sU[r*128 + c + 1] = sZ[r*128 + c + 1] + acc[ni][hf*2+1];
                }
        }
        __syncthreads();   // all hmix reads of XQu/XVu done before Xq overwrites

        // ---- Xq / Xv gemms (A = Ph horizontal Hn) ----
        for (int qv = 0; qv < 2; qv++) {
            float acc[4][4]; ZERO_ACC(acc);
            int off = qv ? WOFF_VAL(l) : WOFF_LIN(l);
            gemm_stream(Ph, Pl, g_WH + off, g_WL + off, 128, 8, wst,
                        acc, tid, lane, wm, wn);
            float* dst = qv ? sXv : sXq;
            #pragma unroll
            for (int ni = 0; ni < 4; ni++)
                #pragma unroll
                for (int hf = 0; hf < 2; hf++) {
                    int r = wm + hf*8 + (lane >> 2);
                    int c = wn + ni*8 + 2*(lane & 3);
                    dst[r*XST + c]     = acc[ni][hf*2+0];
                    dst[r*XST + c + 1] = acc[ni][hf*2+1];
                }
        }
        __syncthreads();

        // ---- attention: warp = (head, quarter); Y packed -> Ph/Pl ----
        {
            const int h = wid & 3;
            const int quarter = wid >> 2;
            float* myexp = sexp + wid * 64;
            int*   mydst = sdstW + wid * 64;
            for (int i = quarter; i < NN; i += 4) {
                const int e0  = g_rowptr[i];
                const int deg = g_rowptr[i+1] - e0;
                const float* qrow = sXq + i*XST + h*32;
                float vmax = -1e30f;
                for (int kb = 0; kb < deg; kb += 32) {
                    const int k = kb + lane;
                    const bool ok = (k < deg);
                    const int j = ok ? dstI[e0 + k] : 0;
                    const float* jrow = sXq + j*XST + h*32;
                    float accd = 0.f;
                    #pragma unroll
                    for (int d = 0; d < 32; d++) {
                        float x = qrow[d] + jrow[d];
                        x = (x > 0.f) ? x : 0.2f * x;
                        accd = fmaf(x, sa[h*32 + d], accd);
                    }
                    float v = ok ? (accd + g_logA0[e0 + k]) : -1e30f;
                    if (ok) { myexp[k] = v; mydst[k] = j; }
                    vmax = fmaxf(vmax, v);
                }
                #pragma unroll
                for (int o = 16; o; o >>= 1)
                    vmax = fmaxf(vmax, __shfl_xor_sync(0xffffffffu, vmax, o));
                __syncwarp();
                float den = 0.f;
                for (int kb = 0; kb < deg; kb += 32) {
                    const int k = kb + lane;
                    if (k < deg) {
                        float ev = expf(myexp[k] - vmax);
                        myexp[k] = ev;
                        den += ev;
                    }
                }
                #pragma unroll
                for (int o = 16; o; o >>= 1) den += __shfl_xor_sync(0xffffffffu, den, o);
                __syncwarp();
                const float inv = 1.f / den;
                float y = 0.f;
                #pragma unroll 4
                for (int k = 0; k < deg; k++)
                    y = fmaf(myexp[k], sXv[mydst[k]*XST + h*32 + lane], y);
                float yf = y * inv;
                float yp = __shfl_down_sync(0xffffffffu, yf, 1);
                if (!(lane & 1)) {
                    uint32_t hh, ll;
                    split_pair(yf, yp, hh, ll);
                    Ph[i*PST + h*16 + (lane >> 1)] = hh;
                    Pl[i*PST + h*16 + (lane >> 1)] = ll;
                }
                __syncwarp();
            }
        }

        // ---- Wout gemm: sU += Y@Wout ----
        {
            float acc[4][4]; ZERO_ACC(acc);
            gemm_stream(Ph, Pl, g_WH + WOFF_OUT(l), g_WL + WOFF_OUT(l), 128, 8, wst,
                        acc, tid, lane, wm, wn);
            #pragma unroll
            for (int ni = 0; ni < 4; ni++)
                #pragma unroll
                for (int hf = 0; hf < 2; hf++) {
                    int r = wm + hf*8 + (lane >> 2);
                    int c = wn + ni*8 + 2*(lane & 3);
                    sU[r*128 + c]     += acc[ni][hf*2+0];
                    sU[r*128 + c + 1] += acc[ni][hf*2+1];
                }
        }
        __syncthreads();

        // ---- gate + LN2 -> sU gated (in place); packed LN2 -> Ph/Pl ----
        {
            float4 w1v = *(const float4*)(g1w + l*128 + lane*4);
            float4 b1v = *(const float4*)(g1b + l*128 + lane*4);
            float4 w2v = *(const float4*)(g2w + l*128 + lane*4);
            float4 l2g = *(const float4*)(ln2g + l*128 + lane*4);
            float4 l2b = *(const float4*)(ln2b + l*128 + lane*4);
            float g2bs = g2b[l];
            #pragma unroll
            for (int q = 0; q < 4; q++) {
                int r = wid * 4 + q;
                float4* u4 = (float4*)(sU + r*128);
                float4 x = u4[lane];
                float s  = x.x + x.y + x.z + x.w;
                float ss = x.x*x.x + x.y*x.y + x.z*x.z + x.w*x.w;
                #pragma unroll
                for (int o = 16; o; o >>= 1) {
                    s  += __shfl_xor_sync(0xffffffffu, s,  o);
                    ss += __shfl_xor_sync(0xffffffffu, ss, o);
                }
                float m   = s * (1.f/128.f);
                float var = ss * (1.f/128.f) - m*m;
                float accg = 0.f;
                {
                    float t0 = m*w1v.x + b1v.x; accg += (t0/(1.f+expf(-t0)))*w2v.x;
                    float t1 = m*w1v.y + b1v.y; accg += (t1/(1.f+expf(-t1)))*w2v.y;
                    float t2 = m*w1v.z + b1v.z; accg += (t2/(1.f+expf(-t2)))*w2v.z;
                    float t3 = m*w1v.w + b1v.w; accg += (t3/(1.f+expf(-t3)))*w2v.w;
                }
                #pragma unroll
                for (int o = 16; o; o >>= 1) accg += __shfl_xor_sync(0xffffffffu, accg, o);
                float gate = 1.f / (1.f + expf(-(accg + g2bs)));
                float4 vg; vg.x = x.x*gate; vg.y = x.y*gate; vg.z = x.z*gate; vg.w = x.w*gate;
                u4[lane] = vg;
                float mu2 = m * gate;
                float rsg = rsqrtf(var * gate * gate + 1e-5f);
                float4 hn;
                hn.x = (vg.x - mu2)*rsg*l2g.x + l2b.x;
                hn.y = (vg.y - mu2)*rsg*l2g.y + l2b.y;
                hn.z = (vg.z - mu2)*rsg*l2g.z + l2b.z;
                hn.w = (vg.w - mu2)*rsg*l2g.w + l2b.w;
                uint2 t2p; uint32_t a, b;
                split_pair(hn.x, hn.y, t2p.x, a); split_pair(hn.z, hn.w, t2p.y, b);
                *(uint2*)&Ph[r*PST + lane*2] = t2p;
                t2p.x = a; t2p.y = b;
                *(uint2*)&Pl[r*PST + lane*2] = t2p;
            }
        }
        __syncthreads();

        // ---- MLP (chunked): Z = silu(LN2@Wm1+bm1)@Wm2 + bm2 + Ug ----
        {
            float accZ[4][4]; ZERO_ACC(accZ);
            for (int ch = 0; ch < 4; ch++) {
                float accM[4][4]; ZERO_ACC(accM);
                gemm_stream(Ph, Pl,
                            g_WH + WOFF_M1(l) + ch*128, g_WL + WOFF_M1(l) + ch*128,
                            512, 8, wst, accM, tid, lane, wm, wn);
                #pragma unroll
                for (int ni = 0; ni < 4; ni++)
                    #pragma unroll
                    for (int hf = 0; hf < 2; hf++) {
                        int r = wm + hf*8 + (lane >> 2);
                        int c = wn + ni*8 + 2*(lane & 3);
                        float v0 = accM[ni][hf*2+0] + bm1[l*512 + ch*128 + c];
                        float v1 = accM[ni][hf*2+1] + bm1[l*512 + ch*128 + c + 1];
                        v0 = v0 / (1.f + expf(-v0));
                        v1 = v1 / (1.f + expf(-v1));
                        uint32_t h, lo;
                        split_pair(v0, v1, h, lo);
                        XQu[r*PST + (c >> 1)] = h;
                        XVu[r*PST + (c >> 1)] = lo;
                    }
                gemm_stream(XQu, XVu,
                            g_WH + WOFF_M2(l) + (size_t)(ch*64)*128,
                            g_WL + WOFF_M2(l) + (size_t)(ch*64)*128,
                            128, 8, wst, accZ, tid, lane, wm, wn);
            }
            __syncthreads();
            #pragma unroll
            for (int ni = 0; ni < 4; ni++)
                #pragma unroll
                for (int hf = 0; hf < 2; hf++) {
                    int r = wm + hf*8 + (lane >> 2);
                    int c = wn + ni*8 + 2*(lane & 3);
                    sZ[r*128 + c]     = accZ[ni][hf*2+0] + bm2[l*128 + c]     + sU[r*128 + c];
                    sZ[r*128 + c + 1] = accZ[ni][hf*2+1] + bm2[l*128 + c + 1] + sU[r*128 + c + 1];
                }
        }
        __syncthreads();
    }

    // ---- outputs ----
    {
        float4* zo = (float4*)(Zdst + (size_t)bt * NN * DD);
        const float4* zs = (const float4*)sZ;
        for (int idx = tid; idx < 2048; idx += TPB) zo[idx] = zs[idx];
        if (Sdst) {
            int d = tid & 127, part = tid >> 7;
            float ps = 0.f;
            for (int i = part*16; i < part*16 + 16; i++) ps += sZ[i*128 + d];
            sexp[part*128 + d] = ps;
            __syncthreads();
            if (tid < 128)
                Sdst[(size_t)bt*128 + tid] =
                    (sexp[tid] + sexp[128+tid] + sexp[256+tid] + sexp[384+tid]) * (1.f/64.f);
        }
    }
}

// ---------------- setup kernels ----------------
__global__ void pack_w_kernel(
    const float* __restrict__ Wp, const float* __restrict__ Wlin,
    const float* __restrict__ Wval, const float* __restrict__ Wout,
    const float* __restrict__ Wm1, const float* __restrict__ Wm2)
{
    int idx = blockIdx.x * blockDim.x + threadIdx.x;
    if (idx >= WTOT) return;
    const float* W; int N, off;
    if (idx < 8192) { W = Wp; N = DD; off = idx; }
    else {
        int j = idx - 8192, l = j / WSEG, u = j % WSEG;
        if (u < 8192)       { W = Wlin + (size_t)l*DD*DD; N = DD; off = u; }
        else if (u < 16384) { W = Wval + (size_t)l*DD*DD; N = DD; off = u - 8192; }
        else if (u < 24576) { W = Wout + (size_t)l*DD*DD; N = DD; off = u - 16384; }
        else if (u < 57344) { W = Wm1  + (size_t)l*DD*D4; N = D4; off = u - 24576; }
        else                { W = Wm2  + (size_t)l*D4*DD; N = DD; off = u - 57344; }
    }
    int k2 = off / N, n = off - k2 * N;
    uint32_t h, l2;
    split_pair(W[(size_t)(2*k2) * N + n], W[(size_t)(2*k2+1) * N + n], h, l2);
    g_WH[idx] = h; g_WL[idx] = l2;
}

__global__ void adj_kernel(const float* __restrict__ A0, const float* __restrict__ P,
                           const float* __restrict__ Qm, const float* __restrict__ alphap,
                           float* __restrict__ A)
{
    int i = blockIdx.x, j = threadIdx.x;
    float a0 = A0[i*NN + j];
    float dot = 0.f;
    #pragma unroll
    for (int r = 0; r < 8; r++) dot += P[i*8 + r] * Qm[j*8 + r];
    float sp = (dot > 20.f) ? dot : log1pf(expf(dot));
    float ad = (a0 > 0.f) ? sp : 0.f;
    float a  = a0 * (1.f + alphap[0] * ad);
    __shared__ float sbuf[NN];
    sbuf[j] = a;
    __syncthreads();
    for (int st = 32; st >= 1; st >>= 1) {
        if (j < st) sbuf[j] += sbuf[j + st];
        __syncthreads();
    }
    A[i*NN + j] = a / (sbuf[0] + 1e-8f);
}

__global__ void pack_adj_kernel(const float* __restrict__ A)
{
    int idx = blockIdx.x * blockDim.x + threadIdx.x;
    if (idx >= NN*32) return;
    int i = idx >> 5, j2 = idx & 31;
    uint32_t h, l;
    split_pair(A[i*NN + 2*j2], A[i*NN + 2*j2 + 1], h, l);
    g_AJH[idx] = h; g_AJL[idx] = l;
}

__global__ void rowptr_kernel(const int* __restrict__ src, int E)
{
    int t = threadIdx.x;
    if (t > NN) return;
    int lo = 0, hi = E;
    while (lo < hi) { int mid = (lo + hi) >> 1; if (src[mid] < t) lo = mid + 1; else hi = mid; }
    g_rowptr[t] = lo;
}

__global__ void edge_kernel(const int* __restrict__ src, const int* __restrict__ dst,
                            const float* __restrict__ A0, int E)
{
    int e = blockIdx.x * blockDim.x + threadIdx.x;
    if (e < E) g_logA0[e] = logf(A0[src[e]*NN + dst[e]] + 1e-8f);
}

__global__ void copy_kernel(const float* __restrict__ src, float* __restrict__ dst, int n4)
{
    int i = blockIdx.x * blockDim.x + threadIdx.x;
    if (i < n4) ((float4*)dst)[i] = ((const float4*)src)[i];
}

__global__ void fill0_kernel(float* __restrict__ p, int n)
{
    int i = blockIdx.x * blockDim.x + threadIdx.x;
    if (i < n) p[i] = 0.f;
}

// ---------------- host driver ----------------
extern "C" void kernel_launch(void* const* d_in, const int* in_sizes, int n_in,
                              void* d_out, int out_size)
{
    const float* X     = (const float*)d_in[0];
    const float* Wp    = (const float*)d_in[1];
    const float* bp    = (const float*)d_in[2];
    const float* P     = (const float*)d_in[3];
    const float* Qm    = (const float*)d_in[4];
    const float* alpha = (const float*)d_in[5];
    const float* ln1g  = (const float*)d_in[6];
    const float* ln1b  = (const float*)d_in[7];
    const float* Wlin  = (const float*)d_in[8];
    const float* Wval  = (const float*)d_in[9];
    const float* a_att = (const float*)d_in[10];
    const float* Wout  = (const float*)d_in[11];
    const float* g1w   = (const float*)d_in[12];
    const float* g1b   = (const float*)d_in[13];
    const float* g2w   = (const float*)d_in[14];
    const float* g2b   = (const float*)d_in[15];
    const float* ln2g  = (const float*)d_in[16];
    const float* ln2b  = (const float*)d_in[17];
    const float* Wm1   = (const float*)d_in[18];
    const float* bm1   = (const float*)d_in[19];
    const float* Wm2   = (const float*)d_in[20];
    const float* bm2   = (const float*)d_in[21];
    const float* A0    = (const float*)d_in[22];
    const int*   srcI  = (const int*)d_in[24];
    const int*   dstI  = (const int*)d_in[25];
    int E = in_sizes[24];
    float* out = (float*)d_out;

    float *Z, *A;
    cudaGetSymbolAddress((void**)&Z, g_Z);
    cudaGetSymbolAddress((void**)&A, g_A);

    cudaFuncSetAttribute(fused_kernel, cudaFuncAttributeMaxDynamicSharedMemorySize,
                         SM_TOT * 4);

    const int ZN = NROWS * DD;
    const int SN = NBT * DD;
    const int AN = NN * NN;
    float* Zdst = (out_size >= ZN) ? out : Z;
    float* Sdst = (out_size >= ZN + SN) ? (out + ZN) : nullptr;

    pack_w_kernel<<<(WTOT + 255) / 256, 256>>>(Wp, Wlin, Wval, Wout, Wm1, Wm2);
    adj_kernel<<<NN, NN>>>(A0, P, Qm, alpha, A);
    pack_adj_kernel<<<(NN*32 + 255) / 256, 256>>>(A);
    rowptr_kernel<<<1, 128>>>(srcI, E);
    edge_kernel<<<(E + 127) / 128, 128>>>(srcI, dstI, A0, E);

    fused_kernel<<<NBT, TPB, SM_TOT * 4>>>(
        X, bp, ln1g, ln1b, a_att, g1w, g1b, g2w, g2b,
        ln2g, ln2b, bm1, bm2, dstI, Zdst, Sdst);

    if (out_size >= ZN + SN + AN)
        copy_kernel<<<(AN / 4 + 255) / 256, 256>>>(A, out + ZN + SN, AN / 4);
    int tail = out_size - (ZN + SN + AN);
    if (tail > 0)
        fill0_kernel<<<(tail + 255) / 256, 256>>>(out + ZN + SN + AN, tail);
}